// round 1
// baseline (speedup 1.0000x reference)
#include <cuda_runtime.h>
#include <math.h>
#include <stdint.h>

#define FRAME_LEN 400
#define HOP       160
#define NFFT      512
#define NBINS     257
#define NMEL      80
#define NFRAMES   2998      // 1 + (480000-400)/160
#define NSAMP     480000
#define BATCH     32
#define PREEMPH   0.97f
#define MEL_FLOOR 1.192092955078125e-07f
#define FPB       4          // frames per block
#define BLOCKS_PER_B ((NFRAMES + FPB - 1) / FPB)   // 750
#define F2        NFRAMES                          // rem = 0
#define NOUTF     1499                             // F2/2
#define NOUTF_PAD 1500                             // +1 pad row
#define FEAT_ELEMS ((size_t)BATCH * NOUTF_PAD * 160)   // 7,680,000
#define MASK_ELEMS ((size_t)BATCH * NOUTF_PAD)         // 48,000

// ---------------- device scratch (static; no allocation allowed) -------------
__device__ float  g_feats[(size_t)BATCH * NFRAMES * NMEL];   // [B, F, 80] ~30.7MB
__device__ int    g_melIdx[NBINS * 4];
__device__ float  g_melW[NBINS * 4];
__device__ double g_part[(size_t)BATCH * NMEL * 8 * 2];      // partial sum/sumsq
__device__ float  g_stats[(size_t)BATCH * NMEL * 2];         // mean, invstd

// ---------------- init: sparse mel table ------------------------------------
__global__ void k_build_table(const float* __restrict__ mel_filters) {
    int k = blockIdx.x * blockDim.x + threadIdx.x;
    if (k >= NBINS) return;
    int cnt = 0;
    int   idx[4] = {-1, -1, -1, -1};
    float w[4]   = {0.f, 0.f, 0.f, 0.f};
    for (int m = 0; m < NMEL; m++) {
        float v = mel_filters[k * NMEL + m];
        if (v != 0.0f && cnt < 4) { idx[cnt] = m; w[cnt] = v; cnt++; }
    }
#pragma unroll
    for (int t = 0; t < 4; t++) {
        g_melIdx[k * 4 + t] = idx[t];
        g_melW[k * 4 + t]   = w[t];
    }
}

// ---------------- K1: frames -> FFT -> power -> mel -> log ------------------
__global__ __launch_bounds__(128) void k_frames(
    const float* __restrict__ wav,
    const float* __restrict__ mask,
    const float* __restrict__ window)
{
    __shared__ float  sx[(FPB - 1) * HOP + FRAME_LEN];   // 880
    __shared__ float  sm[(FPB - 1) * HOP + FRAME_LEN];
    __shared__ float  swin[FRAME_LEN];
    __shared__ float2 sfft[NFFT];
    __shared__ float2 stw[NFFT / 2];
    __shared__ int    sIdx[NBINS * 4];
    __shared__ float  sW[NBINS * 4];
    __shared__ float  smel[NMEL];
    __shared__ float  sred[8];

    const int tid = threadIdx.x;
    const int b   = blockIdx.x / BLOCKS_PER_B;
    const int f0  = (blockIdx.x % BLOCKS_PER_B) * FPB;
    const int nf  = min(FPB, NFRAMES - f0);
    const int nload = (nf - 1) * HOP + FRAME_LEN;

    const float* wb = wav  + (size_t)b * NSAMP + (size_t)f0 * HOP;
    const float* mb = mask + (size_t)b * NSAMP + (size_t)f0 * HOP;
    for (int i = tid; i < nload; i += 128) {
        sx[i] = wb[i] * 32768.0f;
        sm[i] = mb[i];
    }
    for (int i = tid; i < FRAME_LEN; i += 128) swin[i] = window[i];
    for (int i = tid; i < NBINS * 4; i += 128) { sIdx[i] = g_melIdx[i]; sW[i] = g_melW[i]; }
    for (int k = tid; k < NFFT / 2; k += 128) {
        float s, c;
        sincosf(-6.283185307179586f * (float)k / (float)NFFT, &s, &c);
        stw[k] = make_float2(c, s);
    }
    __syncthreads();

    for (int lf = 0; lf < nf; lf++) {
        const float* x  = sx + lf * HOP;
        const float* mm = sm + lf * HOP;

        // ---- frame mean ----
        float s = 0.f;
        for (int j = tid; j < FRAME_LEN; j += 128) s += x[j];
#pragma unroll
        for (int o = 16; o > 0; o >>= 1) s += __shfl_down_sync(0xffffffffu, s, o);
        if ((tid & 31) == 0) sred[tid >> 5] = s;
        __syncthreads();
        if (tid == 0) sred[0] = sred[0] + sred[1] + sred[2] + sred[3];
        __syncthreads();
        const float mean = sred[0] * (1.0f / (float)FRAME_LEN);
        __syncthreads();

        // ---- preemph + window + mask, bit-reversed scatter into fft ----
        for (int i = tid; i < NFFT; i += 128) sfft[i] = make_float2(0.f, 0.f);
        __syncthreads();
        for (int j = tid; j < FRAME_LEN; j += 128) {
            float v;
            if (j == 0) v = (x[0] - mean) * (1.0f - PREEMPH);
            else        v = x[j] - PREEMPH * x[j - 1] - (1.0f - PREEMPH) * mean;
            v *= swin[j] * mm[j];
            int r = __brev((unsigned)j) >> 23;   // 9-bit reversal
            sfft[r] = make_float2(v, 0.f);
        }
        __syncthreads();

        // ---- 512-pt radix-2 DIT FFT ----
#pragma unroll
        for (int st = 1; st <= 9; st++) {
            const int half  = 1 << (st - 1);
            const int shift = 9 - st;
#pragma unroll
            for (int i = tid; i < 256; i += 128) {
                const int g    = i >> (st - 1);
                const int p    = i & (half - 1);
                const int base = (g << st) + p;
                const float2 w = stw[p << shift];
                const float2 a = sfft[base];
                const float2 q = sfft[base + half];
                const float2 t = make_float2(q.x * w.x - q.y * w.y,
                                             q.x * w.y + q.y * w.x);
                sfft[base]        = make_float2(a.x + t.x, a.y + t.y);
                sfft[base + half] = make_float2(a.x - t.x, a.y - t.y);
            }
            __syncthreads();
        }

        // ---- power -> sparse mel ----
        if (tid < NMEL) smel[tid] = 0.f;
        __syncthreads();
        for (int k = tid; k < NBINS; k += 128) {
            const float2 v = sfft[k];
            const float p  = v.x * v.x + v.y * v.y;
#pragma unroll
            for (int t = 0; t < 4; t++) {
                const int mi = sIdx[k * 4 + t];
                if (mi >= 0) atomicAdd(&smel[mi], p * sW[k * 4 + t]);
            }
        }
        __syncthreads();
        if (tid < NMEL) {
            const float v = logf(fmaxf(smel[tid], MEL_FLOOR));
            g_feats[((size_t)(b * NFRAMES + f0 + lf)) * NMEL + tid] = v;
        }
        __syncthreads();
    }
}

// ---------------- K2a: partial sum/sumsq over frame chunks ------------------
__global__ __launch_bounds__(160) void k_stats_partial() {
    const int b     = blockIdx.x >> 3;
    const int chunk = blockIdx.x & 7;
    const int tid   = threadIdx.x;
    const int mel   = tid % NMEL;
    const int sub   = tid / NMEL;           // 0 or 1
    const int fs    = chunk * 375;
    const int fe    = min(NFRAMES, fs + 375);

    double s = 0.0, ss = 0.0;
    for (int fr = fs + sub; fr < fe; fr += 2) {
        const float v = g_feats[((size_t)(b * NFRAMES + fr)) * NMEL + mel];
        s  += (double)v;
        ss += (double)v * (double)v;
    }
    __shared__ double sh[160 * 2];
    sh[tid]       = s;
    sh[160 + tid] = ss;
    __syncthreads();
    if (tid < NMEL) {
        const double S  = sh[tid] + sh[tid + 80];
        const double SS = sh[160 + tid] + sh[160 + tid + 80];
        const size_t o  = ((size_t)(b * NMEL + mel) * 8 + chunk) * 2;
        g_part[o]     = S;
        g_part[o + 1] = SS;
    }
}

// ---------------- K2b: finalize mean / invstd -------------------------------
__global__ void k_stats_final() {
    const int i = blockIdx.x * blockDim.x + threadIdx.x;
    if (i >= BATCH * NMEL) return;
    double S = 0.0, SS = 0.0;
#pragma unroll
    for (int c = 0; c < 8; c++) {
        S  += g_part[((size_t)i * 8 + c) * 2];
        SS += g_part[((size_t)i * 8 + c) * 2 + 1];
    }
    const double F    = (double)NFRAMES;
    const double mean = S / F;
    const double var  = (SS - S * S / F) / (F - 1.0);
    g_stats[i * 2]     = (float)mean;
    g_stats[i * 2 + 1] = (float)(1.0 / sqrt(var + 1e-7));
}

// ---------------- K3: normalize, reshape, pad, mask -------------------------
__global__ void k_output(float* __restrict__ out, size_t out_size) {
    const size_t idx = (size_t)blockIdx.x * blockDim.x + threadIdx.x;
    if (idx >= out_size) return;
    float o;
    if (idx < FEAT_ELEMS) {
        const int b  = (int)(idx / ((size_t)NOUTF_PAD * 160));
        const int r  = (int)(idx % ((size_t)NOUTF_PAD * 160));
        const int f2 = r / 160;
        const int c  = r % 160;
        const int fr = 2 * f2 + (c >= 80 ? 1 : 0);
        const int mel = (c >= 80) ? (c - 80) : c;
        if (fr >= NFRAMES) {
            o = 1.0f;   // padding row, constant_values = 1.0
        } else {
            const float v    = g_feats[((size_t)(b * NFRAMES + fr)) * NMEL + mel];
            const float mean = g_stats[(b * NMEL + mel) * 2];
            const float inv  = g_stats[(b * NMEL + mel) * 2 + 1];
            o = (v - mean) * inv;
        }
    } else if (idx < FEAT_ELEMS + MASK_ELEMS) {
        const size_t j = idx - FEAT_ELEMS;
        const int col  = (int)(j % NOUTF_PAD);
        o = (col < NOUTF) ? 1.0f : 0.0f;
    } else {
        o = 0.0f;
    }
    out[idx] = o;
}

// ---------------- launch -----------------------------------------------------
extern "C" void kernel_launch(void* const* d_in, const int* in_sizes, int n_in,
                              void* d_out, int out_size) {
    const float* raw     = (const float*)d_in[0];
    const float* mask    = (const float*)d_in[1];
    const float* melf    = (const float*)d_in[2];
    const float* window  = (const float*)d_in[3];
    float*       out     = (float*)d_out;

    k_build_table<<<(NBINS + 127) / 128, 128>>>(melf);
    k_frames<<<BATCH * BLOCKS_PER_B, 128>>>(raw, mask, window);
    k_stats_partial<<<BATCH * 8, 160>>>();
    k_stats_final<<<(BATCH * NMEL + 127) / 128, 128>>>();
    const size_t os = (size_t)out_size;
    k_output<<<(unsigned)((os + 255) / 256), 256>>>(out, os);
}

// round 2
// speedup vs baseline: 2.1162x; 2.1162x over previous
#include <cuda_runtime.h>
#include <math.h>
#include <stdint.h>

#define FRAME_LEN 400
#define HOP       160
#define NFFT      512
#define NBINS     257
#define NMEL      80
#define NFRAMES   2998
#define NSAMP     480000
#define BATCH     32
#define PREEMPH   0.97f
#define MEL_FLOOR 1.192092955078125e-07f
#define FPB       8
#define BLOCKS_PER_B ((NFRAMES + FPB - 1) / FPB)   // 375
#define NOUTF     1499
#define NOUTF_PAD 1500
#define FEAT_ELEMS ((size_t)BATCH * NOUTF_PAD * 160)
#define MASK_ELEMS ((size_t)BATCH * NOUTF_PAD)
#define MAXW 24          // max bins per mel triangle (actual max ~19)
#define SPAD(x) ((x) + ((x) >> 3))   // smem pad: kills stride-8 bank conflicts

// ---------------- device scratch ---------------------------------------------
__device__ float  g_feats[(size_t)BATCH * NFRAMES * NMEL];
__device__ int    g_melStart[NMEL];
__device__ int    g_melLen[NMEL];
__device__ float  g_melWts[NMEL * MAXW];
__device__ double g_part[(size_t)BATCH * NMEL * 8 * 2];
__device__ float  g_stats[(size_t)BATCH * NMEL * 2];

// ---------------- complex helpers --------------------------------------------
__device__ __forceinline__ float2 cadd(float2 a, float2 b){ return make_float2(a.x+b.x, a.y+b.y); }
__device__ __forceinline__ float2 csub(float2 a, float2 b){ return make_float2(a.x-b.x, a.y-b.y); }
__device__ __forceinline__ float2 cmul(float2 a, float2 b){ return make_float2(a.x*b.x - a.y*b.y, a.x*b.y + a.y*b.x); }
__device__ __forceinline__ float2 crot(float2 a){ return make_float2(a.y, -a.x); }               // *( -i )
__device__ __forceinline__ float2 cw1 (float2 a){ const float c=0.70710678118654752f; return make_float2(c*(a.x+a.y), c*(a.y-a.x)); }   // * (1-i)/sqrt2
__device__ __forceinline__ float2 cw3 (float2 a){ const float c=0.70710678118654752f; return make_float2(c*(a.y-a.x), -c*(a.x+a.y)); }  // * (-1-i)/sqrt2

// forward 8-pt DFT in registers (inputs natural order x0..x7, outputs in place)
__device__ __forceinline__ void dft8(float2* x) {
    float2 b0=x[0], b1=x[4], b2=x[2], b3=x[6], b4=x[1], b5=x[5], b6=x[3], b7=x[7];
    float2 c0=cadd(b0,b1), c1=csub(b0,b1), c2=cadd(b2,b3), c3=csub(b2,b3);
    float2 c4=cadd(b4,b5), c5=csub(b4,b5), c6=cadd(b6,b7), c7=csub(b6,b7);
    float2 r3=crot(c3),  r7=crot(c7);
    float2 d0=cadd(c0,c2), d2=csub(c0,c2), d1=cadd(c1,r3), d3=csub(c1,r3);
    float2 d4=cadd(c4,c6), d6=csub(c4,c6), d5=cadd(c5,r7), d7=csub(c5,r7);
    float2 w5=cw1(d5), r6=crot(d6), w7=cw3(d7);
    x[0]=cadd(d0,d4); x[1]=cadd(d1,w5); x[2]=cadd(d2,r6); x[3]=cadd(d3,w7);
    x[4]=csub(d0,d4); x[5]=csub(d1,w5); x[6]=csub(d2,r6); x[7]=csub(d3,w7);
}

__device__ __forceinline__ int rev8(int n) {   // base-8 digit reversal of 9-bit index
    return ((n & 7) << 6) | (((n >> 3) & 7) << 3) | ((n >> 6) & 7);
}

// ---------------- init: CSR mel table ----------------------------------------
__global__ void k_build_table(const float* __restrict__ mf) {
    int m = blockIdx.x * blockDim.x + threadIdx.x;
    if (m >= NMEL) return;
    int start = -1, last = -1;
    for (int k = 0; k < NBINS; k++) {
        float v = mf[k * NMEL + m];
        if (v != 0.0f) { if (start < 0) start = k; last = k; }
    }
    if (start < 0) { start = 0; last = -1; }
    int len = last - start + 1;
    if (len > MAXW) len = MAXW;
    g_melStart[m] = start;
    g_melLen[m]   = len;
    for (int t = 0; t < MAXW; t++)
        g_melWts[m * MAXW + t] = (t < len) ? mf[(start + t) * NMEL + m] : 0.0f;
}

// ---------------- K1: frames -> packed FFT -> power -> mel -> log ------------
__global__ __launch_bounds__(128) void k_frames(
    const float* __restrict__ wav,
    const float* __restrict__ mask,
    const float* __restrict__ window)
{
    __shared__ float  sx [(FPB - 1) * HOP + FRAME_LEN];   // 1520
    __shared__ float  smk[(FPB - 1) * HOP + FRAME_LEN];
    __shared__ float  swin[FRAME_LEN];
    __shared__ float2 stw[NFFT];                          // W_512^e table
    __shared__ float2 sfft[2][SPAD(NFFT - 1) + 1 + 8];    // 2 FFT slots, padded
    __shared__ float  spow[2][2][NBINS];                  // [slot][frame re/im][bin]
    __shared__ int    sStart[NMEL];
    __shared__ int    sLen[NMEL];
    __shared__ float  sWts[NMEL * MAXW];
    __shared__ float  smeans[FPB];

    const int tid  = threadIdx.x;
    const int b    = blockIdx.x / BLOCKS_PER_B;
    const int f0   = (blockIdx.x % BLOCKS_PER_B) * FPB;
    const int nf   = min(FPB, NFRAMES - f0);              // always even here
    const int nload = (nf - 1) * HOP + FRAME_LEN;

    const float* wb = wav  + (size_t)b * NSAMP + (size_t)f0 * HOP;
    const float* mb = mask + (size_t)b * NSAMP + (size_t)f0 * HOP;
    for (int i = tid; i < nload; i += 128) {
        sx [i] = wb[i] * 32768.0f;
        smk[i] = mb[i];
    }
    for (int i = tid; i < FRAME_LEN; i += 128) swin[i] = window[i];
    for (int i = tid; i < NMEL; i += 128) { sStart[i] = g_melStart[i]; sLen[i] = g_melLen[i]; }
    for (int i = tid; i < NMEL * MAXW; i += 128) sWts[i] = g_melWts[i];
    for (int e = tid; e < NFFT; e += 128) {
        float s, c;
        sincosf(-6.283185307179586f * (float)e / (float)NFFT, &s, &c);
        stw[e] = make_float2(c, s);
    }
    __syncthreads();

    // per-frame means (warp w handles frames w, w+4)
    {
        const int wid = tid >> 5, lane = tid & 31;
        for (int f = wid; f < nf; f += 4) {
            const float* x = sx + f * HOP;
            float s = 0.f;
            for (int j = lane; j < FRAME_LEN; j += 32) s += x[j];
#pragma unroll
            for (int o = 16; o > 0; o >>= 1) s += __shfl_xor_sync(0xffffffffu, s, o);
            if (lane == 0) smeans[f] = s * (1.0f / (float)FRAME_LEN);
        }
    }
    __syncthreads();

    const int npairs = nf >> 1;             // frame pairs (even nf)
    const int slot   = tid >> 6;            // 0: warps 0-1, 1: warps 2-3
    const int il     = tid & 63;            // lane within FFT team

    for (int pr = 0; pr < npairs; pr += 2) {
        const int  myPair   = pr + slot;
        const bool active   = myPair < npairs;

        // ---- scatter both slots (all 128 threads) ----
#pragma unroll
        for (int s = 0; s < 2; s++) {
            const int pairI = pr + s;
            if (pairI < npairs) {
                const int fa = pairI * 2, fb = fa + 1;
                const float ma = smeans[fa], mmb = smeans[fb];
                const float* xa = sx  + fa * HOP;
                const float* xb = sx  + fb * HOP;
                const float* ka = smk + fa * HOP;
                const float* kb = smk + fb * HOP;
                for (int n = tid; n < NFFT; n += 128) {
                    float va = 0.f, vb = 0.f;
                    if (n < FRAME_LEN) {
                        const int nm = n - (n > 0 ? 1 : 0);
                        const float w = swin[n];
                        va = (xa[n] - PREEMPH * xa[nm] - (1.0f - PREEMPH) * ma)  * w * ka[n];
                        vb = (xb[n] - PREEMPH * xb[nm] - (1.0f - PREEMPH) * mmb) * w * kb[n];
                    }
                    sfft[s][SPAD(rev8(n))] = make_float2(va, vb);
                }
            }
        }
        __syncthreads();

        // ---- 3-stage radix-8 DIT FFT (64 threads per slot) ----
        // stage 0: L=1, twiddles all 1
        if (active) {
            float2 x[8];
            const int base = il * 8;
#pragma unroll
            for (int j = 0; j < 8; j++) x[j] = sfft[slot][SPAD(base + j)];
            dft8(x);
#pragma unroll
            for (int j = 0; j < 8; j++) sfft[slot][SPAD(base + j)] = x[j];
        }
        __syncthreads();
        // stage 1: L=8
        if (active) {
            float2 x[8];
            const int p = il & 7, g = il >> 3;
            const int base = g * 64 + p;
#pragma unroll
            for (int j = 0; j < 8; j++) x[j] = sfft[slot][SPAD(base + j * 8)];
#pragma unroll
            for (int j = 1; j < 8; j++) x[j] = cmul(x[j], stw[(j * p) << 3]);
            dft8(x);
#pragma unroll
            for (int j = 0; j < 8; j++) sfft[slot][SPAD(base + j * 8)] = x[j];
        }
        __syncthreads();
        // stage 2: L=64
        if (active) {
            float2 x[8];
            const int p = il;
#pragma unroll
            for (int j = 0; j < 8; j++) x[j] = sfft[slot][SPAD(p + j * 64)];
#pragma unroll
            for (int j = 1; j < 8; j++) x[j] = cmul(x[j], stw[j * p]);
            dft8(x);
#pragma unroll
            for (int j = 0; j < 8; j++) sfft[slot][SPAD(p + j * 64)] = x[j];
        }
        __syncthreads();

        // ---- unpack packed real pair -> power spectra ----
        for (int idx = tid; idx < 2 * NBINS; idx += 128) {
            const int s = idx / NBINS, k = idx % NBINS;
            if (pr + s < npairs) {
                const float2 Z  = sfft[s][SPAD(k)];
                const float2 Zn = sfft[s][SPAD((NFFT - k) & (NFFT - 1))];
                const float ar = Z.x + Zn.x, ai = Z.y - Zn.y;   // 2*Ya
                const float br = Z.y + Zn.y, bi = Zn.x - Z.x;   // 2*Yb
                spow[s][0][k] = 0.25f * (ar * ar + ai * ai);
                spow[s][1][k] = 0.25f * (br * br + bi * bi);
            }
        }
        __syncthreads();

        // ---- CSR mel projection + log -> g_feats ----
        for (int ch = tid; ch < 4 * NMEL; ch += 128) {
            const int s  = ch / (2 * NMEL);
            const int r  = ch % (2 * NMEL);
            const int fr = r / NMEL;
            const int m  = r % NMEL;
            if (pr + s < npairs) {
                const int st = sStart[m], ln = sLen[m];
                float acc = 0.f;
                for (int t = 0; t < ln; t++)
                    acc += spow[s][fr][st + t] * sWts[m * MAXW + t];
                const int frame = f0 + (pr + s) * 2 + fr;
                g_feats[((size_t)(b * NFRAMES + frame)) * NMEL + m] =
                    logf(fmaxf(acc, MEL_FLOOR));
            }
        }
        __syncthreads();
    }
}

// ---------------- K2a: partial sum/sumsq -------------------------------------
__global__ __launch_bounds__(160) void k_stats_partial() {
    const int b     = blockIdx.x >> 3;
    const int chunk = blockIdx.x & 7;
    const int tid   = threadIdx.x;
    const int mel   = tid % NMEL;
    const int sub   = tid / NMEL;
    const int fs    = chunk * 375;
    const int fe    = min(NFRAMES, fs + 375);

    double s = 0.0, ss = 0.0;
    for (int fr = fs + sub; fr < fe; fr += 2) {
        const float v = g_feats[((size_t)(b * NFRAMES + fr)) * NMEL + mel];
        s  += (double)v;
        ss += (double)v * (double)v;
    }
    __shared__ double sh[160 * 2];
    sh[tid]       = s;
    sh[160 + tid] = ss;
    __syncthreads();
    if (tid < NMEL) {
        const double S  = sh[tid] + sh[tid + 80];
        const double SS = sh[160 + tid] + sh[160 + tid + 80];
        const size_t o  = ((size_t)(b * NMEL + mel) * 8 + chunk) * 2;
        g_part[o]     = S;
        g_part[o + 1] = SS;
    }
}

// ---------------- K2b: finalize ----------------------------------------------
__global__ void k_stats_final() {
    const int i = blockIdx.x * blockDim.x + threadIdx.x;
    if (i >= BATCH * NMEL) return;
    double S = 0.0, SS = 0.0;
#pragma unroll
    for (int c = 0; c < 8; c++) {
        S  += g_part[((size_t)i * 8 + c) * 2];
        SS += g_part[((size_t)i * 8 + c) * 2 + 1];
    }
    const double F    = (double)NFRAMES;
    const double mean = S / F;
    const double var  = (SS - S * S / F) / (F - 1.0);
    g_stats[i * 2]     = (float)mean;
    g_stats[i * 2 + 1] = (float)(1.0 / sqrt(var + 1e-7));
}

// ---------------- K3: normalize / reshape / pad / mask -----------------------
__global__ void k_output(float* __restrict__ out, size_t out_size) {
    const size_t idx = (size_t)blockIdx.x * blockDim.x + threadIdx.x;
    if (idx >= out_size) return;
    float o;
    if (idx < FEAT_ELEMS) {
        const int b  = (int)(idx / ((size_t)NOUTF_PAD * 160));
        const int r  = (int)(idx % ((size_t)NOUTF_PAD * 160));
        const int f2 = r / 160;
        const int c  = r % 160;
        const int fr = 2 * f2 + (c >= 80 ? 1 : 0);
        const int mel = (c >= 80) ? (c - 80) : c;
        if (fr >= NFRAMES) {
            o = 1.0f;
        } else {
            const float v    = g_feats[((size_t)(b * NFRAMES + fr)) * NMEL + mel];
            const float mean = g_stats[(b * NMEL + mel) * 2];
            const float inv  = g_stats[(b * NMEL + mel) * 2 + 1];
            o = (v - mean) * inv;
        }
    } else if (idx < FEAT_ELEMS + MASK_ELEMS) {
        const size_t j = idx - FEAT_ELEMS;
        const int col  = (int)(j % NOUTF_PAD);
        o = (col < NOUTF) ? 1.0f : 0.0f;
    } else {
        o = 0.0f;
    }
    out[idx] = o;
}

// ---------------- launch -----------------------------------------------------
extern "C" void kernel_launch(void* const* d_in, const int* in_sizes, int n_in,
                              void* d_out, int out_size) {
    const float* raw    = (const float*)d_in[0];
    const float* mask   = (const float*)d_in[1];
    const float* melf   = (const float*)d_in[2];
    const float* window = (const float*)d_in[3];
    float*       out    = (float*)d_out;

    k_build_table<<<1, 128>>>(melf);
    k_frames<<<BATCH * BLOCKS_PER_B, 128>>>(raw, mask, window);
    k_stats_partial<<<BATCH * 8, 160>>>();
    k_stats_final<<<(BATCH * NMEL + 127) / 128, 128>>>();
    const size_t os = (size_t)out_size;
    k_output<<<(unsigned)((os + 255) / 256), 256>>>(out, os);
}

// round 3
// speedup vs baseline: 2.1409x; 1.0117x over previous
#include <cuda_runtime.h>
#include <math.h>
#include <stdint.h>

#define FRAME_LEN 400
#define HOP       160
#define NFFT      512
#define NBINS     257
#define NMEL      80
#define NFRAMES   2998
#define NSAMP     480000
#define BATCH     32
#define PREEMPH   0.97f
#define MEL_FLOOR 1.192092955078125e-07f
#define FPB       8
#define BLOCKS_PER_B ((NFRAMES + FPB - 1) / FPB)   // 375
#define NOUTF     1499
#define NOUTF_PAD 1500
#define FEAT_ELEMS ((size_t)BATCH * NOUTF_PAD * 160)
#define MASK_ELEMS ((size_t)BATCH * NOUTF_PAD)
#define MAXW 24
#define SPAD(x) ((x) + ((x) >> 3))
#define SLOT_F2 584                 // float2 per FFT slot (SPAD(511)=574, padded)

// ---- shared layout offsets (floats) ----
#define OFF_SX    0
#define OFF_SMK   1520
#define OFF_SWIN  3040
#define OFF_STW   3440              // float2[512]
#define OFF_SPREP 4464              // 8*400
#define OFF_SFFT  7664              // 4 * 584 float2
#define OFF_SPOW  12336             // 4*2*257
#define OFF_SWTS  14392             // 80*24
#define OFF_START 16312             // 80 int
#define OFF_LEN   16392             // 80 int
#define OFF_MEANS 16472             // 8
#define SMEM_FLOATS 16480
#define SMEM_BYTES  (SMEM_FLOATS * 4)

// ---------------- device scratch ---------------------------------------------
__device__ float  g_feats[(size_t)BATCH * NFRAMES * NMEL];
__device__ int    g_melStart[NMEL];
__device__ int    g_melLen[NMEL];
__device__ float  g_melWts[NMEL * MAXW];
__device__ float2 g_twid[NFFT];
__device__ double g_part[(size_t)BATCH * NMEL * 8 * 2];
__device__ float  g_stats[(size_t)BATCH * NMEL * 2];

// ---------------- complex helpers --------------------------------------------
__device__ __forceinline__ float2 cadd(float2 a, float2 b){ return make_float2(a.x+b.x, a.y+b.y); }
__device__ __forceinline__ float2 csub(float2 a, float2 b){ return make_float2(a.x-b.x, a.y-b.y); }
__device__ __forceinline__ float2 cmul(float2 a, float2 b){ return make_float2(a.x*b.x - a.y*b.y, a.x*b.y + a.y*b.x); }
__device__ __forceinline__ float2 crot(float2 a){ return make_float2(a.y, -a.x); }
__device__ __forceinline__ float2 cw1 (float2 a){ const float c=0.70710678118654752f; return make_float2(c*(a.x+a.y), c*(a.y-a.x)); }
__device__ __forceinline__ float2 cw3 (float2 a){ const float c=0.70710678118654752f; return make_float2(c*(a.y-a.x), -c*(a.x+a.y)); }

__device__ __forceinline__ void dft8(float2* x) {
    float2 b0=x[0], b1=x[4], b2=x[2], b3=x[6], b4=x[1], b5=x[5], b6=x[3], b7=x[7];
    float2 c0=cadd(b0,b1), c1=csub(b0,b1), c2=cadd(b2,b3), c3=csub(b2,b3);
    float2 c4=cadd(b4,b5), c5=csub(b4,b5), c6=cadd(b6,b7), c7=csub(b6,b7);
    float2 r3=crot(c3),  r7=crot(c7);
    float2 d0=cadd(c0,c2), d2=csub(c0,c2), d1=cadd(c1,r3), d3=csub(c1,r3);
    float2 d4=cadd(c4,c6), d6=csub(c4,c6), d5=cadd(c5,r7), d7=csub(c5,r7);
    float2 w5=cw1(d5), r6=crot(d6), w7=cw3(d7);
    x[0]=cadd(d0,d4); x[1]=cadd(d1,w5); x[2]=cadd(d2,r6); x[3]=cadd(d3,w7);
    x[4]=csub(d0,d4); x[5]=csub(d1,w5); x[6]=csub(d2,r6); x[7]=csub(d3,w7);
}

// ---------------- init: CSR mel table + twiddles ------------------------------
__global__ void k_build_table(const float* __restrict__ mf) {
    const int t = threadIdx.x;
    if (t < NFFT) {
        double s, c;
        sincos(-6.283185307179586476925287 * (double)t / (double)NFFT, &s, &c);
        g_twid[t] = make_float2((float)c, (float)s);
    }
    if (t < NMEL) {
        int start = -1, last = -1;
        for (int k = 0; k < NBINS; k++) {
            float v = mf[k * NMEL + t];
            if (v != 0.0f) { if (start < 0) start = k; last = k; }
        }
        if (start < 0) { start = 0; last = -1; }
        int len = last - start + 1;
        if (len > MAXW) len = MAXW;
        g_melStart[t] = start;
        g_melLen[t]   = len;
        for (int q = 0; q < MAXW; q++)
            g_melWts[t * MAXW + q] = (q < len) ? mf[(start + q) * NMEL + t] : 0.0f;
    }
}

// ---------------- K1 ----------------------------------------------------------
__global__ __launch_bounds__(256) void k_frames(
    const float* __restrict__ wav,
    const float* __restrict__ mask,
    const float* __restrict__ window)
{
    extern __shared__ float smemf[];
    float*  sx    = smemf + OFF_SX;
    float*  smk   = smemf + OFF_SMK;
    float*  swin  = smemf + OFF_SWIN;
    float2* stw   = (float2*)(smemf + OFF_STW);
    float*  sprep = smemf + OFF_SPREP;
    float2* sfftA = (float2*)(smemf + OFF_SFFT);
    float*  spow  = smemf + OFF_SPOW;
    float*  sWts  = smemf + OFF_SWTS;
    int*    sStart= (int*)(smemf + OFF_START);
    int*    sLen  = (int*)(smemf + OFF_LEN);
    float*  smeans= smemf + OFF_MEANS;

    const int tid  = threadIdx.x;
    const int b    = blockIdx.x / BLOCKS_PER_B;
    const int f0   = (blockIdx.x % BLOCKS_PER_B) * FPB;
    const int nf   = min(FPB, NFRAMES - f0);
    const int npairs = nf >> 1;               // nf always even (2998 = 374*8+6)
    const int nload  = (nf - 1) * HOP + FRAME_LEN;

    const float* wb = wav  + (size_t)b * NSAMP + (size_t)f0 * HOP;
    const float* mb = mask + (size_t)b * NSAMP + (size_t)f0 * HOP;
    for (int i = tid; i < nload; i += 256) {
        sx [i] = wb[i] * 32768.0f;
        smk[i] = mb[i];
    }
    for (int i = tid; i < FRAME_LEN; i += 256) swin[i] = window[i];
    for (int i = tid; i < NFFT; i += 256)      stw[i]  = g_twid[i];
    for (int i = tid; i < NMEL; i += 256)      { sStart[i] = g_melStart[i]; sLen[i] = g_melLen[i]; }
    for (int i = tid; i < NMEL * MAXW; i += 256) sWts[i] = g_melWts[i];
    __syncthreads();

    // ---- per-frame means: warp w handles frame w ----
    {
        const int wid = tid >> 5, lane = tid & 31;
        if (wid < nf) {
            const float* x = sx + wid * HOP;
            float s = 0.f;
            for (int j = lane; j < FRAME_LEN; j += 32) s += x[j];
#pragma unroll
            for (int o = 16; o > 0; o >>= 1) s += __shfl_xor_sync(0xffffffffu, s, o);
            if (lane == 0) smeans[wid] = s * (1.0f / (float)FRAME_LEN);
        }
    }
    __syncthreads();

    // ---- preemph + window + mask -> sprep[f][n] ----
    for (int i = tid; i < nf * FRAME_LEN; i += 256) {
        const int f = i / FRAME_LEN;
        const int n = i - f * FRAME_LEN;
        const float* x = sx + f * HOP;
        const int nm = n - (n > 0 ? 1 : 0);
        const float v = (x[n] - PREEMPH * x[nm] - (1.0f - PREEMPH) * smeans[f])
                        * swin[n] * smk[f * HOP + n];
        sprep[f * FRAME_LEN + n] = v;
    }
    __syncthreads();

    const int slot = tid >> 6;                 // 0..3 = pair index
    const int il   = tid & 63;
    float2* sfft   = sfftA + slot * SLOT_F2;
    const bool act = slot < npairs;

    // ---- stage 0: gather natural-order (digit-reversed) + dft8 ----
    if (act) {
        const float* pa = sprep + (slot * 2)     * FRAME_LEN;
        const float* pb = sprep + (slot * 2 + 1) * FRAME_LEN;
        float2 x[8];
        const int lo = 8 * (il & 7) + (il >> 3);   // n = 64j + lo
#pragma unroll
        for (int j = 0; j < 8; j++) {
            const int n = 64 * j + lo;
            const float va = (n < FRAME_LEN) ? pa[n] : 0.f;
            const float vb = (n < FRAME_LEN) ? pb[n] : 0.f;
            x[j] = make_float2(va, vb);
        }
        dft8(x);
        const int base = il * 8;
#pragma unroll
        for (int j = 0; j < 8; j++) sfft[SPAD(base + j)] = x[j];
    }
    __syncthreads();

    // ---- stage 1 ----
    if (act) {
        float2 x[8];
        const int p = il & 7, g = il >> 3;
        const int base = g * 64 + p;
#pragma unroll
        for (int j = 0; j < 8; j++) x[j] = sfft[SPAD(base + j * 8)];
#pragma unroll
        for (int j = 1; j < 8; j++) x[j] = cmul(x[j], stw[(j * p) << 3]);
        dft8(x);
#pragma unroll
        for (int j = 0; j < 8; j++) sfft[SPAD(base + j * 8)] = x[j];
    }
    __syncthreads();

    // ---- stage 2 ----
    if (act) {
        float2 x[8];
        const int p = il;
#pragma unroll
        for (int j = 0; j < 8; j++) x[j] = sfft[SPAD(p + j * 64)];
#pragma unroll
        for (int j = 1; j < 8; j++) x[j] = cmul(x[j], stw[j * p]);
        dft8(x);
#pragma unroll
        for (int j = 0; j < 8; j++) sfft[SPAD(p + j * 64)] = x[j];
    }
    __syncthreads();

    // ---- unpack packed real pair -> power spectra ----
    for (int idx = tid; idx < 4 * NBINS; idx += 256) {
        const int s = idx / NBINS, k = idx - s * NBINS;
        if (s < npairs) {
            const float2* sf = sfftA + s * SLOT_F2;
            const float2 Z  = sf[SPAD(k)];
            const float2 Zn = sf[SPAD((NFFT - k) & (NFFT - 1))];
            const float ar = Z.x + Zn.x, ai = Z.y - Zn.y;
            const float br = Z.y + Zn.y, bi = Zn.x - Z.x;
            spow[(s * 2 + 0) * NBINS + k] = 0.25f * (ar * ar + ai * ai);
            spow[(s * 2 + 1) * NBINS + k] = 0.25f * (br * br + bi * bi);
        }
    }
    __syncthreads();

    // ---- CSR mel projection + log -> g_feats ----
    for (int ch = tid; ch < 4 * 2 * NMEL; ch += 256) {
        const int s  = ch / (2 * NMEL);
        const int r  = ch - s * (2 * NMEL);
        const int fr = r / NMEL;
        const int m  = r - fr * NMEL;
        if (s < npairs) {
            const int st = sStart[m], ln = sLen[m];
            const float* pw = spow + (s * 2 + fr) * NBINS + st;
            float acc = 0.f;
            for (int t = 0; t < ln; t++) acc += pw[t] * sWts[m * MAXW + t];
            const int frame = f0 + s * 2 + fr;
            g_feats[((size_t)(b * NFRAMES + frame)) * NMEL + m] =
                logf(fmaxf(acc, MEL_FLOOR));
        }
    }
}

// ---------------- K2a ---------------------------------------------------------
__global__ __launch_bounds__(160) void k_stats_partial() {
    const int b     = blockIdx.x >> 3;
    const int chunk = blockIdx.x & 7;
    const int tid   = threadIdx.x;
    const int mel   = tid % NMEL;
    const int sub   = tid / NMEL;
    const int fs    = chunk * 375;
    const int fe    = min(NFRAMES, fs + 375);

    double s = 0.0, ss = 0.0;
    for (int fr = fs + sub; fr < fe; fr += 2) {
        const float v = g_feats[((size_t)(b * NFRAMES + fr)) * NMEL + mel];
        s  += (double)v;
        ss += (double)v * (double)v;
    }
    __shared__ double sh[160 * 2];
    sh[tid]       = s;
    sh[160 + tid] = ss;
    __syncthreads();
    if (tid < NMEL) {
        const double S  = sh[tid] + sh[tid + 80];
        const double SS = sh[160 + tid] + sh[160 + tid + 80];
        const size_t o  = ((size_t)(b * NMEL + mel) * 8 + chunk) * 2;
        g_part[o]     = S;
        g_part[o + 1] = SS;
    }
}

// ---------------- K2b ---------------------------------------------------------
__global__ void k_stats_final() {
    const int i = blockIdx.x * blockDim.x + threadIdx.x;
    if (i >= BATCH * NMEL) return;
    double S = 0.0, SS = 0.0;
#pragma unroll
    for (int c = 0; c < 8; c++) {
        S  += g_part[((size_t)i * 8 + c) * 2];
        SS += g_part[((size_t)i * 8 + c) * 2 + 1];
    }
    const double F    = (double)NFRAMES;
    const double mean = S / F;
    const double var  = (SS - S * S / F) / (F - 1.0);
    g_stats[i * 2]     = (float)mean;
    g_stats[i * 2 + 1] = (float)(1.0 / sqrt(var + 1e-7));
}

// ---------------- K3 ----------------------------------------------------------
__global__ void k_output(float* __restrict__ out, size_t out_size) {
    const size_t idx = (size_t)blockIdx.x * blockDim.x + threadIdx.x;
    if (idx >= out_size) return;
    float o;
    if (idx < FEAT_ELEMS) {
        const int b  = (int)(idx / ((size_t)NOUTF_PAD * 160));
        const int r  = (int)(idx % ((size_t)NOUTF_PAD * 160));
        const int f2 = r / 160;
        const int c  = r % 160;
        const int fr = 2 * f2 + (c >= 80 ? 1 : 0);
        const int mel = (c >= 80) ? (c - 80) : c;
        if (fr >= NFRAMES) {
            o = 1.0f;
        } else {
            const float v    = g_feats[((size_t)(b * NFRAMES + fr)) * NMEL + mel];
            const float mean = g_stats[(b * NMEL + mel) * 2];
            const float inv  = g_stats[(b * NMEL + mel) * 2 + 1];
            o = (v - mean) * inv;
        }
    } else if (idx < FEAT_ELEMS + MASK_ELEMS) {
        const size_t j = idx - FEAT_ELEMS;
        const int col  = (int)(j % NOUTF_PAD);
        o = (col < NOUTF) ? 1.0f : 0.0f;
    } else {
        o = 0.0f;
    }
    out[idx] = o;
}

// ---------------- launch -----------------------------------------------------
extern "C" void kernel_launch(void* const* d_in, const int* in_sizes, int n_in,
                              void* d_out, int out_size) {
    const float* raw    = (const float*)d_in[0];
    const float* mask   = (const float*)d_in[1];
    const float* melf   = (const float*)d_in[2];
    const float* window = (const float*)d_in[3];
    float*       out    = (float*)d_out;

    cudaFuncSetAttribute(k_frames, cudaFuncAttributeMaxDynamicSharedMemorySize, SMEM_BYTES);

    k_build_table<<<1, 512>>>(melf);
    k_frames<<<BATCH * BLOCKS_PER_B, 256, SMEM_BYTES>>>(raw, mask, window);
    k_stats_partial<<<BATCH * 8, 160>>>();
    k_stats_final<<<(BATCH * NMEL + 127) / 128, 128>>>();
    const size_t os = (size_t)out_size;
    k_output<<<(unsigned)((os + 255) / 256), 256>>>(out, os);
}

// round 4
// speedup vs baseline: 2.5611x; 1.1963x over previous
#include <cuda_runtime.h>
#include <math.h>
#include <stdint.h>

#define FRAME_LEN 400
#define HOP       160
#define NFFT      512
#define NBINS     257
#define NMEL      80
#define NFRAMES   2998
#define NSAMP     480000
#define BATCH     32
#define PREEMPH   0.97f
#define MEL_FLOOR 1.192092955078125e-07f
#define FPB       8
#define BLOCKS_PER_B ((NFRAMES + FPB - 1) / FPB)   // 375
#define NOUTF     1499
#define NOUTF_PAD 1500
#define FEAT_ELEMS ((size_t)BATCH * NOUTF_PAD * 160)
#define MASK_ELEMS ((size_t)BATCH * NOUTF_PAD)
#define MAXW 24
#define NCHUNK 16
#define CHUNKF 188                    // 16*188 = 3008 >= 2998
#define SPAD(x) ((x) + ((x) >> 3))
#define SLOT_F2 584

// ---- shared layout offsets (floats) ----
#define OFF_SX    0
#define OFF_SMK   1520
#define OFF_SWIN  3040
#define OFF_STW   3440              // float2[512]
#define OFF_SPREP 4464              // 8*400
#define OFF_SFFT  7664              // 4 * 584 float2
#define OFF_SPOW  12336             // 4*2*257
#define OFF_SWTS  14392             // 24*80 (transposed)
#define OFF_START 16312             // 80 int
#define OFF_LEN   16392             // 80 int
#define OFF_MEANS 16472             // 8
#define SMEM_FLOATS 16480
#define SMEM_BYTES  (SMEM_FLOATS * 4)

// ---------------- device scratch ---------------------------------------------
__device__ float  g_feats[(size_t)BATCH * NFRAMES * NMEL];
__device__ int    g_melStart[NMEL];
__device__ int    g_melLen[NMEL];
__device__ float  g_melWtsT[MAXW * NMEL];          // [tap][mel] transposed
__device__ float2 g_twid[NFFT];
__device__ double g_part[(size_t)BATCH * NMEL * NCHUNK * 2];
__device__ float  g_stats[(size_t)BATCH * NMEL * 2];

// ---------------- complex helpers --------------------------------------------
__device__ __forceinline__ float2 cadd(float2 a, float2 b){ return make_float2(a.x+b.x, a.y+b.y); }
__device__ __forceinline__ float2 csub(float2 a, float2 b){ return make_float2(a.x-b.x, a.y-b.y); }
__device__ __forceinline__ float2 cmul(float2 a, float2 b){ return make_float2(a.x*b.x - a.y*b.y, a.x*b.y + a.y*b.x); }
__device__ __forceinline__ float2 crot(float2 a){ return make_float2(a.y, -a.x); }
__device__ __forceinline__ float2 cw1 (float2 a){ const float c=0.70710678118654752f; return make_float2(c*(a.x+a.y), c*(a.y-a.x)); }
__device__ __forceinline__ float2 cw3 (float2 a){ const float c=0.70710678118654752f; return make_float2(c*(a.y-a.x), -c*(a.x+a.y)); }

__device__ __forceinline__ void dft8(float2* x) {
    float2 b0=x[0], b1=x[4], b2=x[2], b3=x[6], b4=x[1], b5=x[5], b6=x[3], b7=x[7];
    float2 c0=cadd(b0,b1), c1=csub(b0,b1), c2=cadd(b2,b3), c3=csub(b2,b3);
    float2 c4=cadd(b4,b5), c5=csub(b4,b5), c6=cadd(b6,b7), c7=csub(b6,b7);
    float2 r3=crot(c3),  r7=crot(c7);
    float2 d0=cadd(c0,c2), d2=csub(c0,c2), d1=cadd(c1,r3), d3=csub(c1,r3);
    float2 d4=cadd(c4,c6), d6=csub(c4,c6), d5=cadd(c5,r7), d7=csub(c5,r7);
    float2 w5=cw1(d5), r6=crot(d6), w7=cw3(d7);
    x[0]=cadd(d0,d4); x[1]=cadd(d1,w5); x[2]=cadd(d2,r6); x[3]=cadd(d3,w7);
    x[4]=csub(d0,d4); x[5]=csub(d1,w5); x[6]=csub(d2,r6); x[7]=csub(d3,w7);
}

// ---------------- init: blocks 0..79 = mel m; blocks 80,81 = twiddles --------
__global__ void k_build_table(const float* __restrict__ mf) {
    const int blk = blockIdx.x;
    const int tid = threadIdx.x;
    if (blk >= NMEL) {
        const int t = (blk - NMEL) * 256 + tid;
        if (t < NFFT) {
            double s, c;
            sincos(-6.283185307179586476925287 * (double)t / (double)NFFT, &s, &c);
            g_twid[t] = make_float2((float)c, (float)s);
        }
        return;
    }
    const int m = blk;
    __shared__ int s_min, s_max;
    if (tid == 0) { s_min = NBINS; s_max = -1; }
    __syncthreads();
    for (int k = tid; k < NBINS; k += 256) {
        if (mf[k * NMEL + m] != 0.0f) {
            atomicMin(&s_min, k);
            atomicMax(&s_max, k);
        }
    }
    __syncthreads();
    int start = s_min, last = s_max;
    if (last < 0) { start = 0; last = -1; }
    int len = last - start + 1;
    if (len > MAXW) len = MAXW;
    if (tid == 0) { g_melStart[m] = start; g_melLen[m] = len; }
    if (tid < MAXW)
        g_melWtsT[tid * NMEL + m] = (tid < len) ? mf[(start + tid) * NMEL + m] : 0.0f;
}

// ---------------- K1 ----------------------------------------------------------
__global__ __launch_bounds__(256) void k_frames(
    const float* __restrict__ wav,
    const float* __restrict__ mask,
    const float* __restrict__ window)
{
    extern __shared__ float smemf[];
    float*  sx    = smemf + OFF_SX;
    float*  smk   = smemf + OFF_SMK;
    float*  swin  = smemf + OFF_SWIN;
    float2* stw   = (float2*)(smemf + OFF_STW);
    float*  sprep = smemf + OFF_SPREP;
    float2* sfftA = (float2*)(smemf + OFF_SFFT);
    float*  spow  = smemf + OFF_SPOW;
    float*  sWtsT = smemf + OFF_SWTS;
    int*    sStart= (int*)(smemf + OFF_START);
    int*    sLen  = (int*)(smemf + OFF_LEN);
    float*  smeans= smemf + OFF_MEANS;

    const int tid  = threadIdx.x;
    const int b    = blockIdx.x / BLOCKS_PER_B;
    const int f0   = (blockIdx.x % BLOCKS_PER_B) * FPB;
    const int nf   = min(FPB, NFRAMES - f0);
    const int npairs = nf >> 1;
    const int nload  = (nf - 1) * HOP + FRAME_LEN;

    const float* wb = wav  + (size_t)b * NSAMP + (size_t)f0 * HOP;
    const float* mb = mask + (size_t)b * NSAMP + (size_t)f0 * HOP;
    for (int i = tid; i < nload; i += 256) {
        sx [i] = wb[i] * 32768.0f;
        smk[i] = mb[i];
    }
    for (int i = tid; i < FRAME_LEN; i += 256) swin[i] = window[i];
    for (int i = tid; i < NFFT; i += 256)      stw[i]  = g_twid[i];
    for (int i = tid; i < NMEL; i += 256)      { sStart[i] = g_melStart[i]; sLen[i] = g_melLen[i]; }
    for (int i = tid; i < NMEL * MAXW; i += 256) sWtsT[i] = g_melWtsT[i];
    __syncthreads();

    // ---- per-frame means ----
    {
        const int wid = tid >> 5, lane = tid & 31;
        if (wid < nf) {
            const float* x = sx + wid * HOP;
            float s = 0.f;
            for (int j = lane; j < FRAME_LEN; j += 32) s += x[j];
#pragma unroll
            for (int o = 16; o > 0; o >>= 1) s += __shfl_xor_sync(0xffffffffu, s, o);
            if (lane == 0) smeans[wid] = s * (1.0f / (float)FRAME_LEN);
        }
    }
    __syncthreads();

    // ---- preemph + window + mask -> sprep ----
    for (int i = tid; i < nf * FRAME_LEN; i += 256) {
        const int f = i / FRAME_LEN;
        const int n = i - f * FRAME_LEN;
        const float* x = sx + f * HOP;
        const int nm = n - (n > 0 ? 1 : 0);
        sprep[i] = (x[n] - PREEMPH * x[nm] - (1.0f - PREEMPH) * smeans[f])
                   * swin[n] * smk[f * HOP + n];
    }
    __syncthreads();

    const int slot = tid >> 6;
    const int il   = tid & 63;
    float2* sfft   = sfftA + slot * SLOT_F2;
    const bool act = slot < npairs;

    // ---- stage 0: gather (digit-reversed) + dft8 ----
    if (act) {
        const float* pa = sprep + (slot * 2)     * FRAME_LEN;
        const float* pb = sprep + (slot * 2 + 1) * FRAME_LEN;
        float2 x[8];
        const int lo = 8 * (il & 7) + (il >> 3);
#pragma unroll
        for (int j = 0; j < 8; j++) {
            const int n = 64 * j + lo;
            x[j] = (n < FRAME_LEN) ? make_float2(pa[n], pb[n]) : make_float2(0.f, 0.f);
        }
        dft8(x);
        const int base = il * 8;
#pragma unroll
        for (int j = 0; j < 8; j++) sfft[SPAD(base + j)] = x[j];
    }
    __syncthreads();

    // ---- stage 1 ----
    if (act) {
        float2 x[8];
        const int p = il & 7, g = il >> 3;
        const int base = g * 64 + p;
#pragma unroll
        for (int j = 0; j < 8; j++) x[j] = sfft[SPAD(base + j * 8)];
#pragma unroll
        for (int j = 1; j < 8; j++) x[j] = cmul(x[j], stw[(j * p) << 3]);
        dft8(x);
#pragma unroll
        for (int j = 0; j < 8; j++) sfft[SPAD(base + j * 8)] = x[j];
    }
    __syncthreads();

    // ---- stage 2 ----
    if (act) {
        float2 x[8];
        const int p = il;
#pragma unroll
        for (int j = 0; j < 8; j++) x[j] = sfft[SPAD(p + j * 64)];
#pragma unroll
        for (int j = 1; j < 8; j++) x[j] = cmul(x[j], stw[j * p]);
        dft8(x);
#pragma unroll
        for (int j = 0; j < 8; j++) sfft[SPAD(p + j * 64)] = x[j];
    }
    __syncthreads();

    // ---- unpack packed real pair -> power spectra ----
    for (int idx = tid; idx < 4 * NBINS; idx += 256) {
        const int s = idx / NBINS, k = idx - s * NBINS;
        if (s < npairs) {
            const float2* sf = sfftA + s * SLOT_F2;
            const float2 Z  = sf[SPAD(k)];
            const float2 Zn = sf[SPAD((NFFT - k) & (NFFT - 1))];
            const float ar = Z.x + Zn.x, ai = Z.y - Zn.y;
            const float br = Z.y + Zn.y, bi = Zn.x - Z.x;
            spow[(s * 2 + 0) * NBINS + k] = 0.25f * (ar * ar + ai * ai);
            spow[(s * 2 + 1) * NBINS + k] = 0.25f * (br * br + bi * bi);
        }
    }
    __syncthreads();

    // ---- CSR mel projection (transposed weights: conflict-free) + log ----
    for (int ch = tid; ch < 4 * 2 * NMEL; ch += 256) {
        const int s  = ch / (2 * NMEL);
        const int r  = ch - s * (2 * NMEL);
        const int fr = r / NMEL;
        const int m  = r - fr * NMEL;
        if (s < npairs) {
            const int st = sStart[m], ln = sLen[m];
            const float* pw = spow + (s * 2 + fr) * NBINS + st;
            float acc = 0.f;
#pragma unroll 4
            for (int t = 0; t < ln; t++) acc += pw[t] * sWtsT[t * NMEL + m];
            const int frame = f0 + s * 2 + fr;
            g_feats[((size_t)(b * NFRAMES + frame)) * NMEL + m] =
                __logf(fmaxf(acc, MEL_FLOOR));
        }
    }
}

// ---------------- K2a ---------------------------------------------------------
__global__ __launch_bounds__(160) void k_stats_partial() {
    const int b     = blockIdx.x / NCHUNK;
    const int chunk = blockIdx.x % NCHUNK;
    const int tid   = threadIdx.x;
    const int mel   = tid % NMEL;
    const int sub   = tid / NMEL;
    const int fs    = chunk * CHUNKF;
    const int fe    = min(NFRAMES, fs + CHUNKF);

    double s = 0.0, ss = 0.0;
    for (int fr = fs + sub; fr < fe; fr += 2) {
        const float v = g_feats[((size_t)(b * NFRAMES + fr)) * NMEL + mel];
        s  += (double)v;
        ss += (double)v * (double)v;
    }
    __shared__ double sh[160 * 2];
    sh[tid]       = s;
    sh[160 + tid] = ss;
    __syncthreads();
    if (tid < NMEL) {
        const double S  = sh[tid] + sh[tid + 80];
        const double SS = sh[160 + tid] + sh[160 + tid + 80];
        const size_t o  = ((size_t)(b * NMEL + mel) * NCHUNK + chunk) * 2;
        g_part[o]     = S;
        g_part[o + 1] = SS;
    }
}

// ---------------- K2b ---------------------------------------------------------
__global__ void k_stats_final() {
    const int i = blockIdx.x * blockDim.x + threadIdx.x;
    if (i >= BATCH * NMEL) return;
    double S = 0.0, SS = 0.0;
#pragma unroll
    for (int c = 0; c < NCHUNK; c++) {
        S  += g_part[((size_t)i * NCHUNK + c) * 2];
        SS += g_part[((size_t)i * NCHUNK + c) * 2 + 1];
    }
    const double F    = (double)NFRAMES;
    const double mean = S / F;
    const double var  = (SS - S * S / F) / (F - 1.0);
    g_stats[i * 2]     = (float)mean;
    g_stats[i * 2 + 1] = (float)(1.0 / sqrt(var + 1e-7));
}

// ---------------- K3 ----------------------------------------------------------
__global__ void k_output(float* __restrict__ out, size_t out_size) {
    const size_t idx = (size_t)blockIdx.x * blockDim.x + threadIdx.x;
    if (idx >= out_size) return;
    float o;
    if (idx < FEAT_ELEMS) {
        const int b  = (int)(idx / ((size_t)NOUTF_PAD * 160));
        const int r  = (int)(idx % ((size_t)NOUTF_PAD * 160));
        const int f2 = r / 160;
        const int c  = r % 160;
        const int fr = 2 * f2 + (c >= 80 ? 1 : 0);
        const int mel = (c >= 80) ? (c - 80) : c;
        if (fr >= NFRAMES) {
            o = 1.0f;
        } else {
            const float v    = g_feats[((size_t)(b * NFRAMES + fr)) * NMEL + mel];
            const float mean = g_stats[(b * NMEL + mel) * 2];
            const float inv  = g_stats[(b * NMEL + mel) * 2 + 1];
            o = (v - mean) * inv;
        }
    } else if (idx < FEAT_ELEMS + MASK_ELEMS) {
        const size_t j = idx - FEAT_ELEMS;
        const int col  = (int)(j % NOUTF_PAD);
        o = (col < NOUTF) ? 1.0f : 0.0f;
    } else {
        o = 0.0f;
    }
    out[idx] = o;
}

// ---------------- launch -----------------------------------------------------
extern "C" void kernel_launch(void* const* d_in, const int* in_sizes, int n_in,
                              void* d_out, int out_size) {
    const float* raw    = (const float*)d_in[0];
    const float* mask   = (const float*)d_in[1];
    const float* melf   = (const float*)d_in[2];
    const float* window = (const float*)d_in[3];
    float*       out    = (float*)d_out;

    cudaFuncSetAttribute(k_frames, cudaFuncAttributeMaxDynamicSharedMemorySize, SMEM_BYTES);

    k_build_table<<<NMEL + 2, 256>>>(melf);
    k_frames<<<BATCH * BLOCKS_PER_B, 256, SMEM_BYTES>>>(raw, mask, window);
    k_stats_partial<<<BATCH * NCHUNK, 160>>>();
    k_stats_final<<<(BATCH * NMEL + 127) / 128, 128>>>();
    const size_t os = (size_t)out_size;
    k_output<<<(unsigned)((os + 255) / 256), 256>>>(out, os);
}

// round 5
// speedup vs baseline: 3.0140x; 1.1768x over previous
#include <cuda_runtime.h>
#include <math.h>
#include <stdint.h>

#define FRAME_LEN 400
#define HOP       160
#define NFFT      512
#define NBINS     257
#define NMEL      80
#define NFRAMES   2998
#define NSAMP     480000
#define BATCH     32
#define PREEMPH   0.97f
#define MEL_FLOOR 1.192092955078125e-07f
#define FPB       8
#define BLOCKS_PER_B ((NFRAMES + FPB - 1) / FPB)   // 375
#define NOUTF     1499
#define NOUTF_PAD 1500
#define FEAT_ELEMS ((size_t)BATCH * NOUTF_PAD * 160)
#define MASK_ELEMS ((size_t)BATCH * NOUTF_PAD)
#define MAXW 24
#define NCHUNK 16
#define CHUNKF 188
#define SPAD(x) ((x) + ((x) >> 3))
#define SLOT_F2 584

// ---- shared layout offsets (floats) ----
#define OFF_SX    0                  // 1520
#define OFF_SWIN  1520               // 400
#define OFF_SPREP 1920               // 3200
#define OFF_SFFT  5120               // 4*584 float2 = 4672
#define OFF_SPOW  9792               // 8*257 = 2056
#define OFF_SWTS  11848              // 24*80 = 1920
#define OFF_START 13768              // 80
#define OFF_LEN   13848              // 80
#define OFF_MEANS 13928              // 8
#define SMEM_FLOATS 13936
#define SMEM_BYTES  (SMEM_FLOATS * 4)   // 55744 B -> 4 blocks/SM

// ---------------- device scratch ---------------------------------------------
__device__ float  g_feats[(size_t)BATCH * NFRAMES * NMEL];
__device__ int    g_melStart[NMEL];
__device__ int    g_melLen[NMEL];
__device__ float  g_melWtsT[MAXW * NMEL];
__device__ double g_part[(size_t)BATCH * NMEL * NCHUNK * 2];
__device__ float  g_stats[(size_t)BATCH * NMEL * 2];

// ---------------- complex helpers --------------------------------------------
__device__ __forceinline__ float2 cadd(float2 a, float2 b){ return make_float2(a.x+b.x, a.y+b.y); }
__device__ __forceinline__ float2 csub(float2 a, float2 b){ return make_float2(a.x-b.x, a.y-b.y); }
__device__ __forceinline__ float2 cmul(float2 a, float2 b){ return make_float2(a.x*b.x - a.y*b.y, a.x*b.y + a.y*b.x); }
__device__ __forceinline__ float2 crot(float2 a){ return make_float2(a.y, -a.x); }
__device__ __forceinline__ float2 cw1 (float2 a){ const float c=0.70710678118654752f; return make_float2(c*(a.x+a.y), c*(a.y-a.x)); }
__device__ __forceinline__ float2 cw3 (float2 a){ const float c=0.70710678118654752f; return make_float2(c*(a.y-a.x), -c*(a.x+a.y)); }

__device__ __forceinline__ void dft8(float2* x) {
    float2 b0=x[0], b1=x[4], b2=x[2], b3=x[6], b4=x[1], b5=x[5], b6=x[3], b7=x[7];
    float2 c0=cadd(b0,b1), c1=csub(b0,b1), c2=cadd(b2,b3), c3=csub(b2,b3);
    float2 c4=cadd(b4,b5), c5=csub(b4,b5), c6=cadd(b6,b7), c7=csub(b6,b7);
    float2 r3=crot(c3),  r7=crot(c7);
    float2 d0=cadd(c0,c2), d2=csub(c0,c2), d1=cadd(c1,r3), d3=csub(c1,r3);
    float2 d4=cadd(c4,c6), d6=csub(c4,c6), d5=cadd(c5,r7), d7=csub(c5,r7);
    float2 w5=cw1(d5), r6=crot(d6), w7=cw3(d7);
    x[0]=cadd(d0,d4); x[1]=cadd(d1,w5); x[2]=cadd(d2,r6); x[3]=cadd(d3,w7);
    x[4]=csub(d0,d4); x[5]=csub(d1,w5); x[6]=csub(d2,r6); x[7]=csub(d3,w7);
}

// apply twiddles exp(-2*pi*i * j*p / L) to x[1..7] via sincos + recurrence
__device__ __forceinline__ void twiddle7(float2* x, float pOverL) {
    float s1, c1;
    __sincosf(-6.283185307179586f * pOverL, &s1, &c1);
    const float2 w1 = make_float2(c1, s1);
    float2 w = w1;
    x[1] = cmul(x[1], w);
#pragma unroll
    for (int j = 2; j < 8; j++) { w = cmul(w, w1); x[j] = cmul(x[j], w); }
}

// ---------------- init: one block per mel -------------------------------------
__global__ void k_build_table(const float* __restrict__ mf) {
    const int m   = blockIdx.x;
    const int tid = threadIdx.x;
    __shared__ int s_min, s_max;
    if (tid == 0) { s_min = NBINS; s_max = -1; }
    __syncthreads();
    for (int k = tid; k < NBINS; k += 256) {
        if (mf[k * NMEL + m] != 0.0f) {
            atomicMin(&s_min, k);
            atomicMax(&s_max, k);
        }
    }
    __syncthreads();
    int start = s_min, last = s_max;
    if (last < 0) { start = 0; last = -1; }
    int len = last - start + 1;
    if (len > MAXW) len = MAXW;
    if (tid == 0) { g_melStart[m] = start; g_melLen[m] = len; }
    if (tid < MAXW)
        g_melWtsT[tid * NMEL + m] = (tid < len) ? mf[(start + tid) * NMEL + m] : 0.0f;
}

// ---------------- K1 ----------------------------------------------------------
__global__ __launch_bounds__(256, 4) void k_frames(
    const float* __restrict__ wav,
    const float* __restrict__ mask,
    const float* __restrict__ window)
{
    extern __shared__ float smemf[];
    float*  sx    = smemf + OFF_SX;
    float*  swin  = smemf + OFF_SWIN;
    float*  sprep = smemf + OFF_SPREP;
    float2* sfftA = (float2*)(smemf + OFF_SFFT);
    float*  spow  = smemf + OFF_SPOW;
    float*  sWtsT = smemf + OFF_SWTS;
    int*    sStart= (int*)(smemf + OFF_START);
    int*    sLen  = (int*)(smemf + OFF_LEN);
    float*  smeans= smemf + OFF_MEANS;

    const int tid  = threadIdx.x;
    const int b    = blockIdx.x / BLOCKS_PER_B;
    const int f0   = (blockIdx.x % BLOCKS_PER_B) * FPB;
    const int nf   = min(FPB, NFRAMES - f0);
    const int npairs = nf >> 1;
    const int nload  = (nf - 1) * HOP + FRAME_LEN;

    const float* wb = wav  + (size_t)b * NSAMP + (size_t)f0 * HOP;
    const float* mb = mask + (size_t)b * NSAMP + (size_t)f0 * HOP;
    for (int i = tid; i < nload; i += 256) sx[i] = wb[i] * 32768.0f;
    for (int i = tid; i < FRAME_LEN; i += 256) swin[i] = window[i];
    for (int i = tid; i < NMEL; i += 256)      { sStart[i] = g_melStart[i]; sLen[i] = g_melLen[i]; }
    for (int i = tid; i < NMEL * MAXW; i += 256) sWtsT[i] = g_melWtsT[i];
    __syncthreads();

    // ---- per-frame means ----
    {
        const int wid = tid >> 5, lane = tid & 31;
        if (wid < nf) {
            const float* x = sx + wid * HOP;
            float s = 0.f;
            for (int j = lane; j < FRAME_LEN; j += 32) s += x[j];
#pragma unroll
            for (int o = 16; o > 0; o >>= 1) s += __shfl_xor_sync(0xffffffffu, s, o);
            if (lane == 0) smeans[wid] = s * (1.0f / (float)FRAME_LEN);
        }
    }
    __syncthreads();

    // ---- preemph + window + mask (mask from gmem) -> sprep ----
    for (int i = tid; i < nf * FRAME_LEN; i += 256) {
        const int f = i / FRAME_LEN;
        const int n = i - f * FRAME_LEN;
        const float* x = sx + f * HOP;
        const int nm = n - (n > 0 ? 1 : 0);
        sprep[i] = (x[n] - PREEMPH * x[nm] - (1.0f - PREEMPH) * smeans[f])
                   * swin[n] * mb[f * HOP + n];
    }
    __syncthreads();

    const int slot = tid >> 6;
    const int il   = tid & 63;
    float2* sfft   = sfftA + slot * SLOT_F2;
    const bool act = slot < npairs;

    // ---- stage 0: gather (digit-reversed) + dft8 ----
    if (act) {
        const float* pa = sprep + (slot * 2)     * FRAME_LEN;
        const float* pb = sprep + (slot * 2 + 1) * FRAME_LEN;
        float2 x[8];
        const int lo = 8 * (il & 7) + (il >> 3);
#pragma unroll
        for (int j = 0; j < 8; j++) {
            const int n = 64 * j + lo;
            x[j] = (n < FRAME_LEN) ? make_float2(pa[n], pb[n]) : make_float2(0.f, 0.f);
        }
        dft8(x);
        const int base = il * 8;
#pragma unroll
        for (int j = 0; j < 8; j++) sfft[SPAD(base + j)] = x[j];
    }
    __syncthreads();

    // ---- stage 1: twiddles exp(-2pi i j p / 64), p = il&7 ----
    if (act) {
        float2 x[8];
        const int p = il & 7, g = il >> 3;
        const int base = g * 64 + p;
#pragma unroll
        for (int j = 0; j < 8; j++) x[j] = sfft[SPAD(base + j * 8)];
        twiddle7(x, (float)p * (1.0f / 64.0f));
        dft8(x);
#pragma unroll
        for (int j = 0; j < 8; j++) sfft[SPAD(base + j * 8)] = x[j];
    }
    __syncthreads();

    // ---- stage 2: twiddles exp(-2pi i j p / 512), p = il ----
    if (act) {
        float2 x[8];
        const int p = il;
#pragma unroll
        for (int j = 0; j < 8; j++) x[j] = sfft[SPAD(p + j * 64)];
        twiddle7(x, (float)p * (1.0f / 512.0f));
        dft8(x);
#pragma unroll
        for (int j = 0; j < 8; j++) sfft[SPAD(p + j * 64)] = x[j];
    }
    __syncthreads();

    // ---- unpack packed real pair -> power spectra ----
    for (int idx = tid; idx < 4 * NBINS; idx += 256) {
        const int s = idx / NBINS, k = idx - s * NBINS;
        if (s < npairs) {
            const float2* sf = sfftA + s * SLOT_F2;
            const float2 Z  = sf[SPAD(k)];
            const float2 Zn = sf[SPAD((NFFT - k) & (NFFT - 1))];
            const float ar = Z.x + Zn.x, ai = Z.y - Zn.y;
            const float br = Z.y + Zn.y, bi = Zn.x - Z.x;
            spow[(s * 2 + 0) * NBINS + k] = 0.25f * (ar * ar + ai * ai);
            spow[(s * 2 + 1) * NBINS + k] = 0.25f * (br * br + bi * bi);
        }
    }
    __syncthreads();

    // ---- CSR mel projection + log ----
    for (int ch = tid; ch < 4 * 2 * NMEL; ch += 256) {
        const int s  = ch / (2 * NMEL);
        const int r  = ch - s * (2 * NMEL);
        const int fr = r / NMEL;
        const int m  = r - fr * NMEL;
        if (s < npairs) {
            const int st = sStart[m], ln = sLen[m];
            const float* pw = spow + (s * 2 + fr) * NBINS + st;
            float acc = 0.f;
#pragma unroll 4
            for (int t = 0; t < ln; t++) acc += pw[t] * sWtsT[t * NMEL + m];
            const int frame = f0 + s * 2 + fr;
            g_feats[((size_t)(b * NFRAMES + frame)) * NMEL + m] =
                __logf(fmaxf(acc, MEL_FLOOR));
        }
    }
}

// ---------------- K2a ---------------------------------------------------------
__global__ __launch_bounds__(160) void k_stats_partial() {
    const int b     = blockIdx.x / NCHUNK;
    const int chunk = blockIdx.x % NCHUNK;
    const int tid   = threadIdx.x;
    const int mel   = tid % NMEL;
    const int sub   = tid / NMEL;
    const int fs    = chunk * CHUNKF;
    const int fe    = min(NFRAMES, fs + CHUNKF);

    double s = 0.0, ss = 0.0;
    for (int fr = fs + sub; fr < fe; fr += 2) {
        const float v = g_feats[((size_t)(b * NFRAMES + fr)) * NMEL + mel];
        s  += (double)v;
        ss += (double)v * (double)v;
    }
    __shared__ double sh[160 * 2];
    sh[tid]       = s;
    sh[160 + tid] = ss;
    __syncthreads();
    if (tid < NMEL) {
        const double S  = sh[tid] + sh[tid + 80];
        const double SS = sh[160 + tid] + sh[160 + tid + 80];
        const size_t o  = ((size_t)(b * NMEL + mel) * NCHUNK + chunk) * 2;
        g_part[o]     = S;
        g_part[o + 1] = SS;
    }
}

// ---------------- K2b ---------------------------------------------------------
__global__ void k_stats_final() {
    const int i = blockIdx.x * blockDim.x + threadIdx.x;
    if (i >= BATCH * NMEL) return;
    double S = 0.0, SS = 0.0;
#pragma unroll
    for (int c = 0; c < NCHUNK; c++) {
        S  += g_part[((size_t)i * NCHUNK + c) * 2];
        SS += g_part[((size_t)i * NCHUNK + c) * 2 + 1];
    }
    const double F    = (double)NFRAMES;
    const double mean = S / F;
    const double var  = (SS - S * S / F) / (F - 1.0);
    g_stats[i * 2]     = (float)mean;
    g_stats[i * 2 + 1] = (float)(1.0 / sqrt(var + 1e-7));
}

// ---------------- K3 ----------------------------------------------------------
__global__ void k_output(float* __restrict__ out, size_t out_size) {
    const size_t idx = (size_t)blockIdx.x * blockDim.x + threadIdx.x;
    if (idx >= out_size) return;
    float o;
    if (idx < FEAT_ELEMS) {
        const int b  = (int)(idx / ((size_t)NOUTF_PAD * 160));
        const int r  = (int)(idx % ((size_t)NOUTF_PAD * 160));
        const int f2 = r / 160;
        const int c  = r % 160;
        const int fr = 2 * f2 + (c >= 80 ? 1 : 0);
        const int mel = (c >= 80) ? (c - 80) : c;
        if (fr >= NFRAMES) {
            o = 1.0f;
        } else {
            const float v    = g_feats[((size_t)(b * NFRAMES + fr)) * NMEL + mel];
            const float mean = g_stats[(b * NMEL + mel) * 2];
            const float inv  = g_stats[(b * NMEL + mel) * 2 + 1];
            o = (v - mean) * inv;
        }
    } else if (idx < FEAT_ELEMS + MASK_ELEMS) {
        const size_t j = idx - FEAT_ELEMS;
        const int col  = (int)(j % NOUTF_PAD);
        o = (col < NOUTF) ? 1.0f : 0.0f;
    } else {
        o = 0.0f;
    }
    out[idx] = o;
}

// ---------------- launch -----------------------------------------------------
extern "C" void kernel_launch(void* const* d_in, const int* in_sizes, int n_in,
                              void* d_out, int out_size) {
    const float* raw    = (const float*)d_in[0];
    const float* mask   = (const float*)d_in[1];
    const float* melf   = (const float*)d_in[2];
    const float* window = (const float*)d_in[3];
    float*       out    = (float*)d_out;

    cudaFuncSetAttribute(k_frames, cudaFuncAttributeMaxDynamicSharedMemorySize, SMEM_BYTES);

    k_build_table<<<NMEL, 256>>>(melf);
    k_frames<<<BATCH * BLOCKS_PER_B, 256, SMEM_BYTES>>>(raw, mask, window);
    k_stats_partial<<<BATCH * NCHUNK, 160>>>();
    k_stats_final<<<(BATCH * NMEL + 127) / 128, 128>>>();
    const size_t os = (size_t)out_size;
    k_output<<<(unsigned)((os + 255) / 256), 256>>>(out, os);
}

// round 6
// speedup vs baseline: 3.5463x; 1.1766x over previous
#include <cuda_runtime.h>
#include <math.h>
#include <stdint.h>

#define FRAME_LEN 400
#define HOP       160
#define NFFT      512
#define NBINS     257
#define NMEL      80
#define NFRAMES   2998
#define NSAMP     480000
#define BATCH     32
#define PREEMPH   0.97f
#define MEL_FLOOR 1.192092955078125e-07f
#define FPB       8
#define BLOCKS_PER_B ((NFRAMES + FPB - 1) / FPB)   // 375
#define NOUTF     1499
#define NOUTF_PAD 1500
#define FEAT_ELEMS ((size_t)BATCH * NOUTF_PAD * 160)
#define MASK_ELEMS ((size_t)BATCH * NOUTF_PAD)
#define MAXW 24
#define NCHUNK 16
#define CHUNKF 188
#define SPAD(x) ((x) + ((x) >> 3))
#define SLOT_F2 584

// ---- shared layout offsets (floats) ----
#define OFF_SX    0                  // 1520
#define OFF_SWIN  1520               // 400
#define OFF_SFFT  1920               // 4*584 float2 = 4672 floats*2 = 9344
#define OFF_SPOW  11264              // 8*257 = 2056
#define OFF_SWTS  13320              // 24*80 = 1920
#define OFF_START 15240              // 80
#define OFF_LEN   15320              // 80
#define OFF_MEANS 15400              // 8
#define SMEM_FLOATS 15408
#define SMEM_BYTES  (SMEM_FLOATS * 4)   // 61632? no: recompute below

// NOTE: OFF_SFFT region holds 4*584 float2 = 2336 float2 = 4672 floats.
// Layout audit: sx[0,1520) win[1520,1920) sfft[1920,6592) spow[6592,8648)
// wts[8648,10568) start[10568,10648) len[10648,10728) means[10728,10736)
#undef OFF_SFFT
#undef OFF_SPOW
#undef OFF_SWTS
#undef OFF_START
#undef OFF_LEN
#undef OFF_MEANS
#undef SMEM_FLOATS
#undef SMEM_BYTES
#define OFF_SFFT  1920
#define OFF_SPOW  6592
#define OFF_SWTS  8648
#define OFF_START 10568
#define OFF_LEN   10648
#define OFF_MEANS 10728
#define SMEM_FLOATS 10736
#define SMEM_BYTES  (SMEM_FLOATS * 4)   // 42944 B -> 5 blocks/SM

// ---------------- device scratch ---------------------------------------------
__device__ float  g_feats[(size_t)BATCH * NFRAMES * NMEL];
__device__ int    g_melStart[NMEL];
__device__ int    g_melLen[NMEL];
__device__ float  g_melWtsT[MAXW * NMEL];
__device__ double g_part[(size_t)BATCH * NMEL * NCHUNK * 2];
__device__ float  g_stats[(size_t)BATCH * NMEL * 2];

// ---------------- complex helpers --------------------------------------------
__device__ __forceinline__ float2 cadd(float2 a, float2 b){ return make_float2(a.x+b.x, a.y+b.y); }
__device__ __forceinline__ float2 csub(float2 a, float2 b){ return make_float2(a.x-b.x, a.y-b.y); }
__device__ __forceinline__ float2 cmul(float2 a, float2 b){ return make_float2(a.x*b.x - a.y*b.y, a.x*b.y + a.y*b.x); }
__device__ __forceinline__ float2 crot(float2 a){ return make_float2(a.y, -a.x); }
__device__ __forceinline__ float2 cw1 (float2 a){ const float c=0.70710678118654752f; return make_float2(c*(a.x+a.y), c*(a.y-a.x)); }
__device__ __forceinline__ float2 cw3 (float2 a){ const float c=0.70710678118654752f; return make_float2(c*(a.y-a.x), -c*(a.x+a.y)); }

__device__ __forceinline__ void dft8(float2* x) {
    float2 b0=x[0], b1=x[4], b2=x[2], b3=x[6], b4=x[1], b5=x[5], b6=x[3], b7=x[7];
    float2 c0=cadd(b0,b1), c1=csub(b0,b1), c2=cadd(b2,b3), c3=csub(b2,b3);
    float2 c4=cadd(b4,b5), c5=csub(b4,b5), c6=cadd(b6,b7), c7=csub(b6,b7);
    float2 r3=crot(c3),  r7=crot(c7);
    float2 d0=cadd(c0,c2), d2=csub(c0,c2), d1=cadd(c1,r3), d3=csub(c1,r3);
    float2 d4=cadd(c4,c6), d6=csub(c4,c6), d5=cadd(c5,r7), d7=csub(c5,r7);
    float2 w5=cw1(d5), r6=crot(d6), w7=cw3(d7);
    x[0]=cadd(d0,d4); x[1]=cadd(d1,w5); x[2]=cadd(d2,r6); x[3]=cadd(d3,w7);
    x[4]=csub(d0,d4); x[5]=csub(d1,w5); x[6]=csub(d2,r6); x[7]=csub(d3,w7);
}

__device__ __forceinline__ void twiddle7(float2* x, float pOverL) {
    float s1, c1;
    __sincosf(-6.283185307179586f * pOverL, &s1, &c1);
    const float2 w1 = make_float2(c1, s1);
    float2 w = w1;
    x[1] = cmul(x[1], w);
#pragma unroll
    for (int j = 2; j < 8; j++) { w = cmul(w, w1); x[j] = cmul(x[j], w); }
}

// ---------------- init: one block per mel -------------------------------------
__global__ void k_build_table(const float* __restrict__ mf) {
    const int m   = blockIdx.x;
    const int tid = threadIdx.x;
    __shared__ int s_min, s_max;
    if (tid == 0) { s_min = NBINS; s_max = -1; }
    __syncthreads();
    for (int k = tid; k < NBINS; k += 256) {
        if (mf[k * NMEL + m] != 0.0f) {
            atomicMin(&s_min, k);
            atomicMax(&s_max, k);
        }
    }
    __syncthreads();
    int start = s_min, last = s_max;
    if (last < 0) { start = 0; last = -1; }
    int len = last - start + 1;
    if (len > MAXW) len = MAXW;
    if (tid == 0) { g_melStart[m] = start; g_melLen[m] = len; }
    if (tid < MAXW)
        g_melWtsT[tid * NMEL + m] = (tid < len) ? mf[(start + tid) * NMEL + m] : 0.0f;
}

// ---------------- K1 ----------------------------------------------------------
__global__ __launch_bounds__(256, 5) void k_frames(
    const float* __restrict__ wav,
    const float* __restrict__ mask,
    const float* __restrict__ window)
{
    extern __shared__ float smemf[];
    float*  sx    = smemf + OFF_SX;
    float*  swin  = smemf + OFF_SWIN;
    float2* sfftA = (float2*)(smemf + OFF_SFFT);
    float*  spow  = smemf + OFF_SPOW;
    float*  sWtsT = smemf + OFF_SWTS;
    int*    sStart= (int*)(smemf + OFF_START);
    int*    sLen  = (int*)(smemf + OFF_LEN);
    float*  smeans= smemf + OFF_MEANS;

    const int tid  = threadIdx.x;
    const int b    = blockIdx.x / BLOCKS_PER_B;
    const int f0   = (blockIdx.x % BLOCKS_PER_B) * FPB;
    const int nf   = min(FPB, NFRAMES - f0);
    const int npairs = nf >> 1;
    const int nload  = (nf - 1) * HOP + FRAME_LEN;

    const float* wb = wav  + (size_t)b * NSAMP + (size_t)f0 * HOP;
    const float* mb = mask + (size_t)b * NSAMP + (size_t)f0 * HOP;
    for (int i = tid; i < nload; i += 256) sx[i] = wb[i] * 32768.0f;
    for (int i = tid; i < FRAME_LEN; i += 256) swin[i] = window[i];
    for (int i = tid; i < NMEL; i += 256)      { sStart[i] = g_melStart[i]; sLen[i] = g_melLen[i]; }
    for (int i = tid; i < NMEL * MAXW; i += 256) sWtsT[i] = g_melWtsT[i];
    __syncthreads();

    // ---- per-frame means ----
    {
        const int wid = tid >> 5, lane = tid & 31;
        if (wid < nf) {
            const float* x = sx + wid * HOP;
            float s = 0.f;
            for (int j = lane; j < FRAME_LEN; j += 32) s += x[j];
#pragma unroll
            for (int o = 16; o > 0; o >>= 1) s += __shfl_xor_sync(0xffffffffu, s, o);
            if (lane == 0) smeans[wid] = s * (1.0f / (float)FRAME_LEN);
        }
    }
    __syncthreads();

    const int slot = tid >> 6;
    const int il   = tid & 63;
    float2* sfft   = sfftA + slot * SLOT_F2;
    const bool act = slot < npairs;

    // ---- stage 0: fused preemph/window/mask + digit-reversed gather + dft8 ----
    if (act) {
        const int fa = slot * 2, fb = fa + 1;
        const float* xa = sx + fa * HOP;
        const float* xb = sx + fb * HOP;
        const float* ga = mb + fa * HOP;   // mask (gmem, L1-cached)
        const float* gb2= mb + fb * HOP;
        const float ca = (1.0f - PREEMPH) * smeans[fa];
        const float cb = (1.0f - PREEMPH) * smeans[fb];
        float2 x[8];
        const int lo = 8 * (il & 7) + (il >> 3);
#pragma unroll
        for (int j = 0; j < 8; j++) {
            const int n = 64 * j + lo;
            if (n < FRAME_LEN) {
                const int nm = n - (n > 0 ? 1 : 0);
                const float wv = swin[n];
                const float va = (xa[n] - PREEMPH * xa[nm] - ca) * wv * ga[n];
                const float vb = (xb[n] - PREEMPH * xb[nm] - cb) * wv * gb2[n];
                x[j] = make_float2(va, vb);
            } else {
                x[j] = make_float2(0.f, 0.f);
            }
        }
        dft8(x);
        const int base = il * 8;
#pragma unroll
        for (int j = 0; j < 8; j++) sfft[SPAD(base + j)] = x[j];
    }
    __syncthreads();

    // ---- stage 1 ----
    if (act) {
        float2 x[8];
        const int p = il & 7, g = il >> 3;
        const int base = g * 64 + p;
#pragma unroll
        for (int j = 0; j < 8; j++) x[j] = sfft[SPAD(base + j * 8)];
        twiddle7(x, (float)p * (1.0f / 64.0f));
        dft8(x);
#pragma unroll
        for (int j = 0; j < 8; j++) sfft[SPAD(base + j * 8)] = x[j];
    }
    __syncthreads();

    // ---- stage 2 ----
    if (act) {
        float2 x[8];
        const int p = il;
#pragma unroll
        for (int j = 0; j < 8; j++) x[j] = sfft[SPAD(p + j * 64)];
        twiddle7(x, (float)p * (1.0f / 512.0f));
        dft8(x);
#pragma unroll
        for (int j = 0; j < 8; j++) sfft[SPAD(p + j * 64)] = x[j];
    }
    __syncthreads();

    // ---- unpack packed real pair -> power spectra ----
    for (int idx = tid; idx < 4 * NBINS; idx += 256) {
        const int s = idx / NBINS, k = idx - s * NBINS;
        if (s < npairs) {
            const float2* sf = sfftA + s * SLOT_F2;
            const float2 Z  = sf[SPAD(k)];
            const float2 Zn = sf[SPAD((NFFT - k) & (NFFT - 1))];
            const float ar = Z.x + Zn.x, ai = Z.y - Zn.y;
            const float br = Z.y + Zn.y, bi = Zn.x - Z.x;
            spow[(s * 2 + 0) * NBINS + k] = 0.25f * (ar * ar + ai * ai);
            spow[(s * 2 + 1) * NBINS + k] = 0.25f * (br * br + bi * bi);
        }
    }
    __syncthreads();

    // ---- CSR mel projection + log ----
    for (int ch = tid; ch < 4 * 2 * NMEL; ch += 256) {
        const int s  = ch / (2 * NMEL);
        const int r  = ch - s * (2 * NMEL);
        const int fr = r / NMEL;
        const int m  = r - fr * NMEL;
        if (s < npairs) {
            const int st = sStart[m], ln = sLen[m];
            const float* pw = spow + (s * 2 + fr) * NBINS + st;
            float acc = 0.f;
#pragma unroll 4
            for (int t = 0; t < ln; t++) acc += pw[t] * sWtsT[t * NMEL + m];
            const int frame = f0 + s * 2 + fr;
            g_feats[((size_t)(b * NFRAMES + frame)) * NMEL + m] =
                __logf(fmaxf(acc, MEL_FLOOR));
        }
    }
}

// ---------------- K2a ---------------------------------------------------------
__global__ __launch_bounds__(160) void k_stats_partial() {
    const int b     = blockIdx.x / NCHUNK;
    const int chunk = blockIdx.x % NCHUNK;
    const int tid   = threadIdx.x;
    const int mel   = tid % NMEL;
    const int sub   = tid / NMEL;
    const int fs    = chunk * CHUNKF;
    const int fe    = min(NFRAMES, fs + CHUNKF);

    double s = 0.0, ss = 0.0;
    for (int fr = fs + sub; fr < fe; fr += 2) {
        const float v = g_feats[((size_t)(b * NFRAMES + fr)) * NMEL + mel];
        s  += (double)v;
        ss += (double)v * (double)v;
    }
    __shared__ double sh[160 * 2];
    sh[tid]       = s;
    sh[160 + tid] = ss;
    __syncthreads();
    if (tid < NMEL) {
        const double S  = sh[tid] + sh[tid + 80];
        const double SS = sh[160 + tid] + sh[160 + tid + 80];
        const size_t o  = ((size_t)(b * NMEL + mel) * NCHUNK + chunk) * 2;
        g_part[o]     = S;
        g_part[o + 1] = SS;
    }
}

// ---------------- K2b ---------------------------------------------------------
__global__ void k_stats_final() {
    const int i = blockIdx.x * blockDim.x + threadIdx.x;
    if (i >= BATCH * NMEL) return;
    double S = 0.0, SS = 0.0;
#pragma unroll
    for (int c = 0; c < NCHUNK; c++) {
        S  += g_part[((size_t)i * NCHUNK + c) * 2];
        SS += g_part[((size_t)i * NCHUNK + c) * 2 + 1];
    }
    const double F    = (double)NFRAMES;
    const double mean = S / F;
    const double var  = (SS - S * S / F) / (F - 1.0);
    g_stats[i * 2]     = (float)mean;
    g_stats[i * 2 + 1] = (float)(1.0 / sqrt(var + 1e-7));
}

// ---------------- K3 ----------------------------------------------------------
__global__ void k_output(float* __restrict__ out, size_t out_size) {
    const size_t idx = (size_t)blockIdx.x * blockDim.x + threadIdx.x;
    if (idx >= out_size) return;
    float o;
    if (idx < FEAT_ELEMS) {
        const int b  = (int)(idx / ((size_t)NOUTF_PAD * 160));
        const int r  = (int)(idx % ((size_t)NOUTF_PAD * 160));
        const int f2 = r / 160;
        const int c  = r % 160;
        const int fr = 2 * f2 + (c >= 80 ? 1 : 0);
        const int mel = (c >= 80) ? (c - 80) : c;
        if (fr >= NFRAMES) {
            o = 1.0f;
        } else {
            const float v    = g_feats[((size_t)(b * NFRAMES + fr)) * NMEL + mel];
            const float mean = g_stats[(b * NMEL + mel) * 2];
            const float inv  = g_stats[(b * NMEL + mel) * 2 + 1];
            o = (v - mean) * inv;
        }
    } else if (idx < FEAT_ELEMS + MASK_ELEMS) {
        const size_t j = idx - FEAT_ELEMS;
        const int col  = (int)(j % NOUTF_PAD);
        o = (col < NOUTF) ? 1.0f : 0.0f;
    } else {
        o = 0.0f;
    }
    out[idx] = o;
}

// ---------------- launch -----------------------------------------------------
extern "C" void kernel_launch(void* const* d_in, const int* in_sizes, int n_in,
                              void* d_out, int out_size) {
    const float* raw    = (const float*)d_in[0];
    const float* mask   = (const float*)d_in[1];
    const float* melf   = (const float*)d_in[2];
    const float* window = (const float*)d_in[3];
    float*       out    = (float*)d_out;

    cudaFuncSetAttribute(k_frames, cudaFuncAttributeMaxDynamicSharedMemorySize, SMEM_BYTES);

    k_build_table<<<NMEL, 256>>>(melf);
    k_frames<<<BATCH * BLOCKS_PER_B, 256, SMEM_BYTES>>>(raw, mask, window);
    k_stats_partial<<<BATCH * NCHUNK, 160>>>();
    k_stats_final<<<(BATCH * NMEL + 127) / 128, 128>>>();
    const size_t os = (size_t)out_size;
    k_output<<<(unsigned)((os + 255) / 256), 256>>>(out, os);
}

// round 7
// speedup vs baseline: 3.8179x; 1.0766x over previous
#include <cuda_runtime.h>
#include <math.h>
#include <stdint.h>

#define FRAME_LEN 400
#define HOP       160
#define NFFT      512
#define NBINS     257
#define NMEL      80
#define NFRAMES   2998
#define NSAMP     480000
#define BATCH     32
#define PREEMPH   0.97f
#define MEL_FLOOR 1.192092955078125e-07f
#define FPB       8
#define BLOCKS_PER_B ((NFRAMES + FPB - 1) / FPB)   // 375
#define NOUTF     1499
#define NOUTF_PAD 1500
#define FEAT_ELEMS ((size_t)BATCH * NOUTF_PAD * 160)
#define MASK_ELEMS ((size_t)BATCH * NOUTF_PAD)
#define MAXW 24
#define SPAD(x) ((x) + ((x) >> 3))
#define SLOT_F2 584

// ---- shared layout (floats) ----
// sx[0,1520) win[1520,1920) sfft[1920,6592) spow[6592,8648)
// wts[8648,10568) start[10568,10648) len[10648,10728) means[10728,10736)
// sfeat overlays sfft region (640 floats, used after sfft is dead)
#define OFF_SX    0
#define OFF_SWIN  1520
#define OFF_SFFT  1920
#define OFF_SPOW  6592
#define OFF_SWTS  8648
#define OFF_START 10568
#define OFF_LEN   10648
#define OFF_MEANS 10728
#define SMEM_FLOATS 10736
#define SMEM_BYTES  (SMEM_FLOATS * 4)   // 42944 B -> 5 blocks/SM

// ---------------- device scratch ---------------------------------------------
__device__ float         g_feats[(size_t)BATCH * NFRAMES * NMEL];
__device__ int           g_melStart[NMEL];
__device__ int           g_melLen[NMEL];
__device__ float         g_melWtsT[MAXW * NMEL];
__device__ double        g_sumd [BATCH * NMEL];
__device__ double        g_sumsqd[BATCH * NMEL];
__device__ float         g_stats[BATCH * NMEL * 2];
__device__ unsigned int  g_done;

// ---------------- complex helpers --------------------------------------------
__device__ __forceinline__ float2 cadd(float2 a, float2 b){ return make_float2(a.x+b.x, a.y+b.y); }
__device__ __forceinline__ float2 csub(float2 a, float2 b){ return make_float2(a.x-b.x, a.y-b.y); }
__device__ __forceinline__ float2 cmul(float2 a, float2 b){ return make_float2(a.x*b.x - a.y*b.y, a.x*b.y + a.y*b.x); }
__device__ __forceinline__ float2 crot(float2 a){ return make_float2(a.y, -a.x); }
__device__ __forceinline__ float2 cw1 (float2 a){ const float c=0.70710678118654752f; return make_float2(c*(a.x+a.y), c*(a.y-a.x)); }
__device__ __forceinline__ float2 cw3 (float2 a){ const float c=0.70710678118654752f; return make_float2(c*(a.y-a.x), -c*(a.x+a.y)); }

__device__ __forceinline__ void dft8(float2* x) {
    float2 b0=x[0], b1=x[4], b2=x[2], b3=x[6], b4=x[1], b5=x[5], b6=x[3], b7=x[7];
    float2 c0=cadd(b0,b1), c1=csub(b0,b1), c2=cadd(b2,b3), c3=csub(b2,b3);
    float2 c4=cadd(b4,b5), c5=csub(b4,b5), c6=cadd(b6,b7), c7=csub(b6,b7);
    float2 r3=crot(c3),  r7=crot(c7);
    float2 d0=cadd(c0,c2), d2=csub(c0,c2), d1=cadd(c1,r3), d3=csub(c1,r3);
    float2 d4=cadd(c4,c6), d6=csub(c4,c6), d5=cadd(c5,r7), d7=csub(c5,r7);
    float2 w5=cw1(d5), r6=crot(d6), w7=cw3(d7);
    x[0]=cadd(d0,d4); x[1]=cadd(d1,w5); x[2]=cadd(d2,r6); x[3]=cadd(d3,w7);
    x[4]=csub(d0,d4); x[5]=csub(d1,w5); x[6]=csub(d2,r6); x[7]=csub(d3,w7);
}

__device__ __forceinline__ void twiddle7(float2* x, float pOverL) {
    float s1, c1;
    __sincosf(-6.283185307179586f * pOverL, &s1, &c1);
    const float2 w1 = make_float2(c1, s1);
    float2 w = w1;
    x[1] = cmul(x[1], w);
#pragma unroll
    for (int j = 2; j < 8; j++) { w = cmul(w, w1); x[j] = cmul(x[j], w); }
}

// ---------------- init: one block per mel; block 0 zeroes accumulators -------
__global__ void k_build_table(const float* __restrict__ mf) {
    const int m   = blockIdx.x;
    const int tid = threadIdx.x;
    if (m == 0) {
        for (int i = tid; i < BATCH * NMEL; i += 256) {
            g_sumd[i]   = 0.0;
            g_sumsqd[i] = 0.0;
        }
        if (tid == 0) g_done = 0u;
    }
    __shared__ int s_min, s_max;
    if (tid == 0) { s_min = NBINS; s_max = -1; }
    __syncthreads();
    for (int k = tid; k < NBINS; k += 256) {
        if (mf[k * NMEL + m] != 0.0f) {
            atomicMin(&s_min, k);
            atomicMax(&s_max, k);
        }
    }
    __syncthreads();
    int start = s_min, last = s_max;
    if (last < 0) { start = 0; last = -1; }
    int len = last - start + 1;
    if (len > MAXW) len = MAXW;
    if (tid == 0) { g_melStart[m] = start; g_melLen[m] = len; }
    if (tid < MAXW)
        g_melWtsT[tid * NMEL + m] = (tid < len) ? mf[(start + tid) * NMEL + m] : 0.0f;
}

// ---------------- K1 ----------------------------------------------------------
__global__ __launch_bounds__(256, 5) void k_frames(
    const float* __restrict__ wav,
    const float* __restrict__ mask,
    const float* __restrict__ window)
{
    extern __shared__ float smemf[];
    float*  sx    = smemf + OFF_SX;
    float*  swin  = smemf + OFF_SWIN;
    float2* sfftA = (float2*)(smemf + OFF_SFFT);
    float*  sfeat = smemf + OFF_SFFT;          // overlay: valid after unpack
    float*  spow  = smemf + OFF_SPOW;
    float*  sWtsT = smemf + OFF_SWTS;
    int*    sStart= (int*)(smemf + OFF_START);
    int*    sLen  = (int*)(smemf + OFF_LEN);
    float*  smeans= smemf + OFF_MEANS;

    const int tid  = threadIdx.x;
    const int b    = blockIdx.x / BLOCKS_PER_B;
    const int f0   = (blockIdx.x % BLOCKS_PER_B) * FPB;
    const int nf   = min(FPB, NFRAMES - f0);
    const int npairs = nf >> 1;
    const int nload  = (nf - 1) * HOP + FRAME_LEN;

    const float* wb = wav  + (size_t)b * NSAMP + (size_t)f0 * HOP;
    const float* mb = mask + (size_t)b * NSAMP + (size_t)f0 * HOP;
    for (int i = tid; i < nload; i += 256) sx[i] = wb[i] * 32768.0f;
    for (int i = tid; i < FRAME_LEN; i += 256) swin[i] = window[i];
    for (int i = tid; i < NMEL; i += 256)      { sStart[i] = g_melStart[i]; sLen[i] = g_melLen[i]; }
    for (int i = tid; i < NMEL * MAXW; i += 256) sWtsT[i] = g_melWtsT[i];
    __syncthreads();

    // ---- per-frame means ----
    {
        const int wid = tid >> 5, lane = tid & 31;
        if (wid < nf) {
            const float* x = sx + wid * HOP;
            float s = 0.f;
            for (int j = lane; j < FRAME_LEN; j += 32) s += x[j];
#pragma unroll
            for (int o = 16; o > 0; o >>= 1) s += __shfl_xor_sync(0xffffffffu, s, o);
            if (lane == 0) smeans[wid] = s * (1.0f / (float)FRAME_LEN);
        }
    }
    __syncthreads();

    const int slot = tid >> 6;
    const int il   = tid & 63;
    float2* sfft   = sfftA + slot * SLOT_F2;
    const bool act = slot < npairs;

    // ---- stage 0: fused preemph/window/mask + digit-reversed gather + dft8 ----
    if (act) {
        const int fa = slot * 2, fb = fa + 1;
        const float* xa = sx + fa * HOP;
        const float* xb = sx + fb * HOP;
        const float* ga = mb + fa * HOP;
        const float* gb2= mb + fb * HOP;
        const float ca = (1.0f - PREEMPH) * smeans[fa];
        const float cb = (1.0f - PREEMPH) * smeans[fb];
        float2 x[8];
        const int lo = 8 * (il & 7) + (il >> 3);
#pragma unroll
        for (int j = 0; j < 8; j++) {
            const int n = 64 * j + lo;
            if (n < FRAME_LEN) {
                const int nm = n - (n > 0 ? 1 : 0);
                const float wv = swin[n];
                const float va = (xa[n] - PREEMPH * xa[nm] - ca) * wv * ga[n];
                const float vb = (xb[n] - PREEMPH * xb[nm] - cb) * wv * gb2[n];
                x[j] = make_float2(va, vb);
            } else {
                x[j] = make_float2(0.f, 0.f);
            }
        }
        dft8(x);
        const int base = il * 8;
#pragma unroll
        for (int j = 0; j < 8; j++) sfft[SPAD(base + j)] = x[j];
    }
    __syncthreads();

    // ---- stage 1 ----
    if (act) {
        float2 x[8];
        const int p = il & 7, g = il >> 3;
        const int base = g * 64 + p;
#pragma unroll
        for (int j = 0; j < 8; j++) x[j] = sfft[SPAD(base + j * 8)];
        twiddle7(x, (float)p * (1.0f / 64.0f));
        dft8(x);
#pragma unroll
        for (int j = 0; j < 8; j++) sfft[SPAD(base + j * 8)] = x[j];
    }
    __syncthreads();

    // ---- stage 2 ----
    if (act) {
        float2 x[8];
        const int p = il;
#pragma unroll
        for (int j = 0; j < 8; j++) x[j] = sfft[SPAD(p + j * 64)];
        twiddle7(x, (float)p * (1.0f / 512.0f));
        dft8(x);
#pragma unroll
        for (int j = 0; j < 8; j++) sfft[SPAD(p + j * 64)] = x[j];
    }
    __syncthreads();

    // ---- unpack packed real pair -> power spectra ----
    for (int idx = tid; idx < 4 * NBINS; idx += 256) {
        const int s = idx / NBINS, k = idx - s * NBINS;
        if (s < npairs) {
            const float2* sf = sfftA + s * SLOT_F2;
            const float2 Z  = sf[SPAD(k)];
            const float2 Zn = sf[SPAD((NFFT - k) & (NFFT - 1))];
            const float ar = Z.x + Zn.x, ai = Z.y - Zn.y;
            const float br = Z.y + Zn.y, bi = Zn.x - Z.x;
            spow[(s * 2 + 0) * NBINS + k] = 0.25f * (ar * ar + ai * ai);
            spow[(s * 2 + 1) * NBINS + k] = 0.25f * (br * br + bi * bi);
        }
    }
    __syncthreads();

    // ---- CSR mel projection + log -> g_feats + sfeat (sfft now dead) ----
    for (int ch = tid; ch < 4 * 2 * NMEL; ch += 256) {
        const int s  = ch / (2 * NMEL);
        const int r  = ch - s * (2 * NMEL);
        const int fr = r / NMEL;
        const int m  = r - fr * NMEL;
        float v = 0.0f;
        if (s < npairs) {
            const int st = sStart[m], ln = sLen[m];
            const float* pw = spow + (s * 2 + fr) * NBINS + st;
            float acc = 0.f;
#pragma unroll 4
            for (int t = 0; t < ln; t++) acc += pw[t] * sWtsT[t * NMEL + m];
            v = __logf(fmaxf(acc, MEL_FLOOR));
            const int frame = f0 + s * 2 + fr;
            g_feats[((size_t)(b * NFRAMES + frame)) * NMEL + m] = v;
        }
        sfeat[ch] = v;        // ch == (s*2+fr)*80 + m
    }
    __syncthreads();

    // ---- block-level stats reduction + double atomics ----
    if (tid < NMEL) {
        float s = 0.f, ss = 0.f;
#pragma unroll
        for (int r = 0; r < FPB; r++) {
            const float v = sfeat[r * NMEL + tid];
            s  += v;
            ss += v * v;
        }
        atomicAdd(&g_sumd  [b * NMEL + tid], (double)s);
        atomicAdd(&g_sumsqd[b * NMEL + tid], (double)ss);
    }

    // ---- last block finalizes mean/invstd ----
    __shared__ int s_last;
    __syncthreads();
    if (tid == 0) {
        __threadfence();
        const unsigned int old = atomicAdd(&g_done, 1u);
        s_last = (old == (unsigned int)(gridDim.x - 1));
    }
    __syncthreads();
    if (s_last) {
        for (int i = tid; i < BATCH * NMEL; i += 256) {
            const double S  = __ldcg(&g_sumd[i]);
            const double SS = __ldcg(&g_sumsqd[i]);
            const double F    = (double)NFRAMES;
            const double mean = S / F;
            const double var  = (SS - S * S / F) / (F - 1.0);
            g_stats[i * 2]     = (float)mean;
            g_stats[i * 2 + 1] = (float)(1.0 / sqrt(var + 1e-7));
        }
    }
}

// ---------------- K3 ----------------------------------------------------------
__global__ void k_output(float* __restrict__ out, size_t out_size) {
    const size_t idx = (size_t)blockIdx.x * blockDim.x + threadIdx.x;
    if (idx >= out_size) return;
    float o;
    if (idx < FEAT_ELEMS) {
        const int b  = (int)(idx / ((size_t)NOUTF_PAD * 160));
        const int r  = (int)(idx % ((size_t)NOUTF_PAD * 160));
        const int f2 = r / 160;
        const int c  = r % 160;
        const int fr = 2 * f2 + (c >= 80 ? 1 : 0);
        const int mel = (c >= 80) ? (c - 80) : c;
        if (fr >= NFRAMES) {
            o = 1.0f;
        } else {
            const float v    = g_feats[((size_t)(b * NFRAMES + fr)) * NMEL + mel];
            const float mean = g_stats[(b * NMEL + mel) * 2];
            const float inv  = g_stats[(b * NMEL + mel) * 2 + 1];
            o = (v - mean) * inv;
        }
    } else if (idx < FEAT_ELEMS + MASK_ELEMS) {
        const size_t j = idx - FEAT_ELEMS;
        const int col  = (int)(j % NOUTF_PAD);
        o = (col < NOUTF) ? 1.0f : 0.0f;
    } else {
        o = 0.0f;
    }
    out[idx] = o;
}

// ---------------- launch -----------------------------------------------------
extern "C" void kernel_launch(void* const* d_in, const int* in_sizes, int n_in,
                              void* d_out, int out_size) {
    const float* raw    = (const float*)d_in[0];
    const float* mask   = (const float*)d_in[1];
    const float* melf   = (const float*)d_in[2];
    const float* window = (const float*)d_in[3];
    float*       out    = (float*)d_out;

    cudaFuncSetAttribute(k_frames, cudaFuncAttributeMaxDynamicSharedMemorySize, SMEM_BYTES);

    k_build_table<<<NMEL, 256>>>(melf);
    k_frames<<<BATCH * BLOCKS_PER_B, 256, SMEM_BYTES>>>(raw, mask, window);
    const size_t os = (size_t)out_size;
    k_output<<<(unsigned)((os + 255) / 256), 256>>>(out, os);
}

// round 8
// speedup vs baseline: 4.3007x; 1.1265x over previous
#include <cuda_runtime.h>
#include <math.h>
#include <stdint.h>

#define FRAME_LEN 400
#define HOP       160
#define NFFT      512
#define NBINS     257
#define NMEL      80
#define NFRAMES   2998
#define NSAMP     480000
#define BATCH     32
#define PREEMPH   0.97f
#define MEL_FLOOR 1.192092955078125e-07f
#define FPB       8
#define BLOCKS_PER_B ((NFRAMES + FPB - 1) / FPB)   // 375
#define NOUTF     1499
#define NOUTF_PAD 1500
#define FEAT_ELEMS ((size_t)BATCH * NOUTF_PAD * 160)   // 7,680,000
#define MASK_ELEMS ((size_t)BATCH * NOUTF_PAD)
#define MAXW 24
#define SPAD(x) ((x) + ((x) >> 3))
#define SLOT_F2 584

// ---- shared layout (floats): sx[0,1520) sfft[1520,6192) spow[6192,8248) means[8248,8256)
#define OFF_SX    0
#define OFF_SFFT  1520
#define OFF_SPOW  6192
#define OFF_MEANS 8248
#define SMEM_FLOATS 8256
#define SMEM_BYTES  (SMEM_FLOATS * 4)    // 33024 B -> 6 blocks/SM

// ---------------- device scratch ---------------------------------------------
__device__ float         g_feats[(size_t)BATCH * NFRAMES * NMEL];
__device__ int           g_melStart[NMEL];
__device__ int           g_melLen[NMEL];
__device__ float         g_melWtsT[MAXW * NMEL];
__device__ double        g_sumd [BATCH * NMEL];
__device__ double        g_sumsqd[BATCH * NMEL];
__device__ float         g_stats[BATCH * NMEL * 2];
__device__ unsigned int  g_done;

// ---------------- complex helpers --------------------------------------------
__device__ __forceinline__ float2 cadd(float2 a, float2 b){ return make_float2(a.x+b.x, a.y+b.y); }
__device__ __forceinline__ float2 csub(float2 a, float2 b){ return make_float2(a.x-b.x, a.y-b.y); }
__device__ __forceinline__ float2 cmul(float2 a, float2 b){ return make_float2(a.x*b.x - a.y*b.y, a.x*b.y + a.y*b.x); }
__device__ __forceinline__ float2 crot(float2 a){ return make_float2(a.y, -a.x); }
__device__ __forceinline__ float2 cw1 (float2 a){ const float c=0.70710678118654752f; return make_float2(c*(a.x+a.y), c*(a.y-a.x)); }
__device__ __forceinline__ float2 cw3 (float2 a){ const float c=0.70710678118654752f; return make_float2(c*(a.y-a.x), -c*(a.x+a.y)); }

__device__ __forceinline__ void dft8(float2* x) {
    float2 b0=x[0], b1=x[4], b2=x[2], b3=x[6], b4=x[1], b5=x[5], b6=x[3], b7=x[7];
    float2 c0=cadd(b0,b1), c1=csub(b0,b1), c2=cadd(b2,b3), c3=csub(b2,b3);
    float2 c4=cadd(b4,b5), c5=csub(b4,b5), c6=cadd(b6,b7), c7=csub(b6,b7);
    float2 r3=crot(c3),  r7=crot(c7);
    float2 d0=cadd(c0,c2), d2=csub(c0,c2), d1=cadd(c1,r3), d3=csub(c1,r3);
    float2 d4=cadd(c4,c6), d6=csub(c4,c6), d5=cadd(c5,r7), d7=csub(c5,r7);
    float2 w5=cw1(d5), r6=crot(d6), w7=cw3(d7);
    x[0]=cadd(d0,d4); x[1]=cadd(d1,w5); x[2]=cadd(d2,r6); x[3]=cadd(d3,w7);
    x[4]=csub(d0,d4); x[5]=csub(d1,w5); x[6]=csub(d2,r6); x[7]=csub(d3,w7);
}

__device__ __forceinline__ void twiddle7(float2* x, float pOverL) {
    float s1, c1;
    __sincosf(-6.283185307179586f * pOverL, &s1, &c1);
    const float2 w1 = make_float2(c1, s1);
    float2 w = w1;
    x[1] = cmul(x[1], w);
#pragma unroll
    for (int j = 2; j < 8; j++) { w = cmul(w, w1); x[j] = cmul(x[j], w); }
}

// ---------------- init: one block per mel; block 0 zeroes accumulators -------
__global__ void k_build_table(const float* __restrict__ mf) {
    const int m   = blockIdx.x;
    const int tid = threadIdx.x;
    if (m == 0) {
        for (int i = tid; i < BATCH * NMEL; i += 256) {
            g_sumd[i]   = 0.0;
            g_sumsqd[i] = 0.0;
        }
        if (tid == 0) g_done = 0u;
    }
    __shared__ int s_min, s_max;
    if (tid == 0) { s_min = NBINS; s_max = -1; }
    __syncthreads();
    for (int k = tid; k < NBINS; k += 256) {
        if (mf[k * NMEL + m] != 0.0f) {
            atomicMin(&s_min, k);
            atomicMax(&s_max, k);
        }
    }
    __syncthreads();
    int start = s_min, last = s_max;
    if (last < 0) { start = 0; last = -1; }
    int len = last - start + 1;
    if (len > MAXW) len = MAXW;
    if (tid == 0) { g_melStart[m] = start; g_melLen[m] = len; }
    if (tid < MAXW)
        g_melWtsT[tid * NMEL + m] = (tid < len) ? mf[(start + tid) * NMEL + m] : 0.0f;
}

// ---------------- K1 ----------------------------------------------------------
__global__ __launch_bounds__(256, 6) void k_frames(
    const float* __restrict__ wav,
    const float* __restrict__ mask,
    const float* __restrict__ window)
{
    extern __shared__ float smemf[];
    float*  sx    = smemf + OFF_SX;
    float2* sfftA = (float2*)(smemf + OFF_SFFT);
    float*  sfeat = smemf + OFF_SFFT;          // overlay: valid after unpack
    float*  spow  = smemf + OFF_SPOW;
    float*  smeans= smemf + OFF_MEANS;

    const int tid  = threadIdx.x;
    const int b    = blockIdx.x / BLOCKS_PER_B;
    const int f0   = (blockIdx.x % BLOCKS_PER_B) * FPB;
    const int nf   = min(FPB, NFRAMES - f0);
    const int npairs = nf >> 1;
    const int nload  = (nf - 1) * HOP + FRAME_LEN;

    const float* wb = wav  + (size_t)b * NSAMP + (size_t)f0 * HOP;
    const float* mb = mask + (size_t)b * NSAMP + (size_t)f0 * HOP;
    for (int i = tid; i < nload; i += 256) sx[i] = wb[i] * 32768.0f;
    __syncthreads();

    // ---- per-frame means ----
    {
        const int wid = tid >> 5, lane = tid & 31;
        if (wid < nf) {
            const float* x = sx + wid * HOP;
            float s = 0.f;
            for (int j = lane; j < FRAME_LEN; j += 32) s += x[j];
#pragma unroll
            for (int o = 16; o > 0; o >>= 1) s += __shfl_xor_sync(0xffffffffu, s, o);
            if (lane == 0) smeans[wid] = s * (1.0f / (float)FRAME_LEN);
        }
    }
    __syncthreads();

    const int slot = tid >> 6;
    const int il   = tid & 63;
    float2* sfft   = sfftA + slot * SLOT_F2;
    const bool act = slot < npairs;

    // ---- stage 0: fused preemph/window(gmem)/mask(gmem) + gather + dft8 ----
    if (act) {
        const int fa = slot * 2, fb = fa + 1;
        const float* xa = sx + fa * HOP;
        const float* xb = sx + fb * HOP;
        const float* ga = mb + fa * HOP;
        const float* gb2= mb + fb * HOP;
        const float ca = (1.0f - PREEMPH) * smeans[fa];
        const float cb = (1.0f - PREEMPH) * smeans[fb];
        float2 x[8];
        const int lo = 8 * (il & 7) + (il >> 3);
#pragma unroll
        for (int j = 0; j < 8; j++) {
            const int n = 64 * j + lo;
            if (n < FRAME_LEN) {
                const int nm = n - (n > 0 ? 1 : 0);
                const float wv = __ldg(&window[n]);
                const float va = (xa[n] - PREEMPH * xa[nm] - ca) * wv * __ldg(&ga[n]);
                const float vb = (xb[n] - PREEMPH * xb[nm] - cb) * wv * __ldg(&gb2[n]);
                x[j] = make_float2(va, vb);
            } else {
                x[j] = make_float2(0.f, 0.f);
            }
        }
        dft8(x);
        const int base = il * 8;
#pragma unroll
        for (int j = 0; j < 8; j++) sfft[SPAD(base + j)] = x[j];
    }
    __syncthreads();

    // ---- stage 1 ----
    if (act) {
        float2 x[8];
        const int p = il & 7, g = il >> 3;
        const int base = g * 64 + p;
#pragma unroll
        for (int j = 0; j < 8; j++) x[j] = sfft[SPAD(base + j * 8)];
        twiddle7(x, (float)p * (1.0f / 64.0f));
        dft8(x);
#pragma unroll
        for (int j = 0; j < 8; j++) sfft[SPAD(base + j * 8)] = x[j];
    }
    __syncthreads();

    // ---- stage 2 ----
    if (act) {
        float2 x[8];
        const int p = il;
#pragma unroll
        for (int j = 0; j < 8; j++) x[j] = sfft[SPAD(p + j * 64)];
        twiddle7(x, (float)p * (1.0f / 512.0f));
        dft8(x);
#pragma unroll
        for (int j = 0; j < 8; j++) sfft[SPAD(p + j * 64)] = x[j];
    }
    __syncthreads();

    // ---- unpack packed real pair -> power spectra ----
    for (int idx = tid; idx < 4 * NBINS; idx += 256) {
        const int s = idx / NBINS, k = idx - s * NBINS;
        if (s < npairs) {
            const float2* sf = sfftA + s * SLOT_F2;
            const float2 Z  = sf[SPAD(k)];
            const float2 Zn = sf[SPAD((NFFT - k) & (NFFT - 1))];
            const float ar = Z.x + Zn.x, ai = Z.y - Zn.y;
            const float br = Z.y + Zn.y, bi = Zn.x - Z.x;
            spow[(s * 2 + 0) * NBINS + k] = 0.25f * (ar * ar + ai * ai);
            spow[(s * 2 + 1) * NBINS + k] = 0.25f * (br * br + bi * bi);
        }
    }
    __syncthreads();

    // ---- CSR mel projection (weights via L1 from gmem) + log ----
    for (int ch = tid; ch < 4 * 2 * NMEL; ch += 256) {
        const int s  = ch / (2 * NMEL);
        const int r  = ch - s * (2 * NMEL);
        const int fr = r / NMEL;
        const int m  = r - fr * NMEL;
        float v = 0.0f;
        if (s < npairs) {
            const int st = __ldg(&g_melStart[m]);
            const int ln = __ldg(&g_melLen[m]);
            const float* pw = spow + (s * 2 + fr) * NBINS + st;
            float acc = 0.f;
#pragma unroll 4
            for (int t = 0; t < ln; t++) acc += pw[t] * __ldg(&g_melWtsT[t * NMEL + m]);
            v = __logf(fmaxf(acc, MEL_FLOOR));
            const int frame = f0 + s * 2 + fr;
            g_feats[((size_t)(b * NFRAMES + frame)) * NMEL + m] = v;
        }
        sfeat[ch] = v;
    }
    __syncthreads();

    // ---- block-level stats + double atomics ----
    if (tid < NMEL) {
        float s = 0.f, ss = 0.f;
#pragma unroll
        for (int r = 0; r < FPB; r++) {
            const float v = sfeat[r * NMEL + tid];
            s  += v;
            ss += v * v;
        }
        atomicAdd(&g_sumd  [b * NMEL + tid], (double)s);
        atomicAdd(&g_sumsqd[b * NMEL + tid], (double)ss);
    }

    // ---- last block finalizes mean/invstd ----
    __shared__ int s_last;
    __syncthreads();
    if (tid == 0) {
        __threadfence();
        const unsigned int old = atomicAdd(&g_done, 1u);
        s_last = (old == (unsigned int)(gridDim.x - 1));
    }
    __syncthreads();
    if (s_last) {
        for (int i = tid; i < BATCH * NMEL; i += 256) {
            const double S  = __ldcg(&g_sumd[i]);
            const double SS = __ldcg(&g_sumsqd[i]);
            const double F    = (double)NFRAMES;
            const double mean = S / F;
            const double var  = (SS - S * S / F) / (F - 1.0);
            g_stats[i * 2]     = (float)mean;
            g_stats[i * 2 + 1] = (float)(1.0 / sqrt(var + 1e-7));
        }
    }
}

// ---------------- K3: vectorized output ---------------------------------------
__global__ void k_output_feat(float4* __restrict__ out) {
    const size_t q = (size_t)blockIdx.x * blockDim.x + threadIdx.x;   // float4 index
    if (q >= FEAT_ELEMS / 4) return;
    const size_t idx = q * 4;
    const int b  = (int)(idx / ((size_t)NOUTF_PAD * 160));
    const int r  = (int)(idx % ((size_t)NOUTF_PAD * 160));
    const int f2 = r / 160;
    const int c  = r % 160;                 // multiple of 4; segment-safe
    const int fr = 2 * f2 + (c >= 80 ? 1 : 0);
    const int mel = (c >= 80) ? (c - 80) : c;
    float4 o;
    if (fr >= NFRAMES) {
        o = make_float4(1.f, 1.f, 1.f, 1.f);
    } else {
        const float* fv = &g_feats[((size_t)(b * NFRAMES + fr)) * NMEL + mel];
        const float* st = &g_stats[(b * NMEL + mel) * 2];
        o.x = (fv[0] - st[0]) * st[1];
        o.y = (fv[1] - st[2]) * st[3];
        o.z = (fv[2] - st[4]) * st[5];
        o.w = (fv[3] - st[6]) * st[7];
    }
    out[q] = o;
}

__global__ void k_output_mask(float* __restrict__ out, size_t out_size) {
    const size_t j = (size_t)blockIdx.x * blockDim.x + threadIdx.x;
    const size_t idx = FEAT_ELEMS + j;
    if (idx >= out_size) return;
    if (j < MASK_ELEMS) {
        const int col = (int)(j % NOUTF_PAD);
        out[idx] = (col < NOUTF) ? 1.0f : 0.0f;
    } else {
        out[idx] = 0.0f;
    }
}

// ---------------- launch -----------------------------------------------------
extern "C" void kernel_launch(void* const* d_in, const int* in_sizes, int n_in,
                              void* d_out, int out_size) {
    const float* raw    = (const float*)d_in[0];
    const float* mask   = (const float*)d_in[1];
    const float* melf   = (const float*)d_in[2];
    const float* window = (const float*)d_in[3];
    float*       out    = (float*)d_out;

    cudaFuncSetAttribute(k_frames, cudaFuncAttributeMaxDynamicSharedMemorySize, SMEM_BYTES);

    k_build_table<<<NMEL, 256>>>(melf);
    k_frames<<<BATCH * BLOCKS_PER_B, 256, SMEM_BYTES>>>(raw, mask, window);
    const size_t os = (size_t)out_size;
    k_output_feat<<<(unsigned)((FEAT_ELEMS / 4 + 255) / 256), 256>>>((float4*)out);
    if (os > FEAT_ELEMS) {
        const size_t tail = os - FEAT_ELEMS;
        k_output_mask<<<(unsigned)((tail + 255) / 256), 256>>>(out, os);
    }
}